// round 1
// baseline (speedup 1.0000x reference)
#include <cuda_runtime.h>
#include <math.h>

// Problem dims
#define NB   64      // batch
#define NT   128     // time
#define BT   8192    // NB*NT
#define H    1024    // hidden
#define DIN  2048    // dim1+dim2
#define G4   4096    // 4*H
#define NH1  256     // H/4 (MLP hidden)
#define NANS 1000

// ---------------- device scratch (static device globals: no allocation) ----
__device__ float g_X1[(size_t)BT * G4];        // input projection, t-major: [t][b][4H]
__device__ float g_h1[2][NB * H];              // ping-pong (read across CTAs each step)
__device__ float g_c1[NB * H];                 // in-place ok (each (m,j) owned by 1 thread)
__device__ float g_h2[2][NB * H];
__device__ float g_c2[NB * H];
__device__ float g_lstm_out[(size_t)BT * H];   // [b*NT + t][H]
__device__ float g_hid[(size_t)BT * NH1];

__device__ __forceinline__ float sigmoidf_(float x) { return 1.f / (1.f + expf(-x)); }

// ---------------- state init (must re-run every launch for graph replay) ---
__global__ void k_init_state() {
    int i = blockIdx.x * blockDim.x + threadIdx.x;
    if (i < NB * H) {
        g_h1[0][i] = 0.f; g_h2[0][i] = 0.f;
        g_c1[i]    = 0.f; g_c2[i]    = 0.f;
    }
}

// ---------------- K1: X1 = [data1|data2] @ W_ih1^T + b1 ---------------------
// C[8192][4096], A rows K-contig (concat at k=1024, BK=16 never straddles),
// W rows K-contig. Tile 64x64, BK=16, 256 thr, 4x4 per-thread.
// Output rows remapped m=b*128+t -> t*64+b so each step reads a contiguous 1MB slab.
__global__ __launch_bounds__(256) void k_xproj(
    const float* __restrict__ d1, const float* __restrict__ d2,
    const float* __restrict__ W, const float* __restrict__ bias)
{
    __shared__ float As[16][64];
    __shared__ float Bs[16][64];
    const int bm = blockIdx.y * 64;
    const int bn = blockIdx.x * 64;
    const int tid = threadIdx.x;
    const int tm = (tid >> 4) * 4;
    const int tn = (tid & 15) * 4;
    const int lr = tid >> 2;
    const int lk = (tid & 3) * 4;
    float acc[4][4] = {};

    for (int k0 = 0; k0 < DIN; k0 += 16) {
        const float* Arow = (k0 < 1024)
            ? (d1 + (size_t)(bm + lr) * 1024 + k0 + lk)
            : (d2 + (size_t)(bm + lr) * 1024 + (k0 - 1024) + lk);
        float4 av = *(const float4*)Arow;
        As[lk+0][lr] = av.x; As[lk+1][lr] = av.y; As[lk+2][lr] = av.z; As[lk+3][lr] = av.w;
        float4 bv = *(const float4*)(W + (size_t)(bn + lr) * DIN + k0 + lk);
        Bs[lk+0][lr] = bv.x; Bs[lk+1][lr] = bv.y; Bs[lk+2][lr] = bv.z; Bs[lk+3][lr] = bv.w;
        __syncthreads();
#pragma unroll
        for (int kk = 0; kk < 16; kk++) {
            float4 a = *(const float4*)&As[kk][tm];
            float4 b = *(const float4*)&Bs[kk][tn];
            acc[0][0] += a.x*b.x; acc[0][1] += a.x*b.y; acc[0][2] += a.x*b.z; acc[0][3] += a.x*b.w;
            acc[1][0] += a.y*b.x; acc[1][1] += a.y*b.y; acc[1][2] += a.y*b.z; acc[1][3] += a.y*b.w;
            acc[2][0] += a.z*b.x; acc[2][1] += a.z*b.y; acc[2][2] += a.z*b.z; acc[2][3] += a.z*b.w;
            acc[3][0] += a.w*b.x; acc[3][1] += a.w*b.y; acc[3][2] += a.w*b.z; acc[3][3] += a.w*b.w;
        }
        __syncthreads();
    }
#pragma unroll
    for (int i = 0; i < 4; i++) {
        int m  = bm + tm + i;
        int t  = m & (NT - 1);
        int bb = m >> 7;
        float* orow = g_X1 + ((size_t)t * NB + bb) * G4 + bn + tn;
#pragma unroll
        for (int j = 0; j < 4; j++)
            orow[j] = acc[i][j] + bias[bn + tn + j];
    }
}

// ---------------- K2: LSTM layer-1 step --------------------------------------
// gates1[64][4][8-j-block] = h1_prev @ Whh1^T + X1[t]; fused cell update.
// Each CTA owns one 8-wide j block and ALL 4 gates (so the cell epilogue is local).
// Grid 128 CTAs, 256 thr; thread = (mt: 2 rows) x (jt: 1 j) x 4 gates = 8 accs.
__global__ __launch_bounds__(256) void k_lstm1(const float* __restrict__ Whh, int t)
{
    __shared__ float As[16][64];
    __shared__ float Bs[16][32];
    const int j0  = blockIdx.x * 8;
    const int tid = threadIdx.x;
    const int jt  = tid & 7;
    const int mt  = tid >> 3;
    const float* h_in  = g_h1[t & 1];
    float*       h_out = g_h1[(t + 1) & 1];
    const float* Xt = g_X1 + (size_t)t * NB * G4;
    const int lr = tid >> 2;
    const int lk = (tid & 3) * 4;
    float acc[4][2] = {};

    for (int k0 = 0; k0 < H; k0 += 16) {
        float4 av = *(const float4*)(h_in + (size_t)lr * H + k0 + lk);
        As[lk+0][lr] = av.x; As[lk+1][lr] = av.y; As[lk+2][lr] = av.z; As[lk+3][lr] = av.w;
        if (tid < 128) {
            int rr = tid >> 2;               // 0..31 == g*8 + j
            int g = rr >> 3, j = rr & 7;
            float4 bv = *(const float4*)(Whh + (size_t)(g * H + j0 + j) * H + k0 + lk);
            Bs[lk+0][rr] = bv.x; Bs[lk+1][rr] = bv.y; Bs[lk+2][rr] = bv.z; Bs[lk+3][rr] = bv.w;
        }
        __syncthreads();
#pragma unroll
        for (int kk = 0; kk < 16; kk++) {
            float2 a = *(const float2*)&As[kk][mt * 2];
            float b0v = Bs[kk][jt],      b1v = Bs[kk][8 + jt];
            float b2v = Bs[kk][16 + jt], b3v = Bs[kk][24 + jt];
            acc[0][0] += a.x*b0v; acc[0][1] += a.y*b0v;
            acc[1][0] += a.x*b1v; acc[1][1] += a.y*b1v;
            acc[2][0] += a.x*b2v; acc[2][1] += a.y*b2v;
            acc[3][0] += a.x*b3v; acc[3][1] += a.y*b3v;
        }
        __syncthreads();
    }
#pragma unroll
    for (int mi = 0; mi < 2; mi++) {
        int m = mt * 2 + mi;
        int j = j0 + jt;
        const float* xr = Xt + (size_t)m * G4 + j;   // X1 already contains +b1
        float gi = acc[0][mi] + xr[0];
        float gf = acc[1][mi] + xr[1024];
        float gg = acc[2][mi] + xr[2048];
        float go = acc[3][mi] + xr[3072];
        int idx = m * H + j;
        float cn = sigmoidf_(gf) * g_c1[idx] + sigmoidf_(gi) * tanhf(gg);
        g_c1[idx]  = cn;
        h_out[idx] = sigmoidf_(go) * tanhf(cn);
    }
}

// ---------------- K3: LSTM layer-2 step + residual ---------------------------
// gates2 = h1_t @ Wih2^T + h2_prev @ Whh2^T + b2; out[:,t,:] = h2_new + h1_t.
__global__ __launch_bounds__(256) void k_lstm2(
    const float* __restrict__ Wih2, const float* __restrict__ Whh2,
    const float* __restrict__ b2, int t)
{
    __shared__ float As[16][64];
    __shared__ float Bs[16][32];
    const int j0  = blockIdx.x * 8;
    const int tid = threadIdx.x;
    const int jt  = tid & 7;
    const int mt  = tid >> 3;
    const float* h1t = g_h1[(t + 1) & 1];   // written by k_lstm1 at this t
    const float* h2p = g_h2[t & 1];
    float*       h2n = g_h2[(t + 1) & 1];
    const int lr = tid >> 2;
    const int lk = (tid & 3) * 4;
    float acc[4][2] = {};
    const float* Asrc[2] = { h1t,  h2p  };
    const float* Bsrc[2] = { Wih2, Whh2 };

#pragma unroll
    for (int p = 0; p < 2; p++) {
        const float* Ap = Asrc[p];
        const float* Bp = Bsrc[p];
        for (int k0 = 0; k0 < H; k0 += 16) {
            float4 av = *(const float4*)(Ap + (size_t)lr * H + k0 + lk);
            As[lk+0][lr] = av.x; As[lk+1][lr] = av.y; As[lk+2][lr] = av.z; As[lk+3][lr] = av.w;
            if (tid < 128) {
                int rr = tid >> 2;
                int g = rr >> 3, j = rr & 7;
                float4 bv = *(const float4*)(Bp + (size_t)(g * H + j0 + j) * H + k0 + lk);
                Bs[lk+0][rr] = bv.x; Bs[lk+1][rr] = bv.y; Bs[lk+2][rr] = bv.z; Bs[lk+3][rr] = bv.w;
            }
            __syncthreads();
#pragma unroll
            for (int kk = 0; kk < 16; kk++) {
                float2 a = *(const float2*)&As[kk][mt * 2];
                float b0v = Bs[kk][jt],      b1v = Bs[kk][8 + jt];
                float b2v = Bs[kk][16 + jt], b3v = Bs[kk][24 + jt];
                acc[0][0] += a.x*b0v; acc[0][1] += a.y*b0v;
                acc[1][0] += a.x*b1v; acc[1][1] += a.y*b1v;
                acc[2][0] += a.x*b2v; acc[2][1] += a.y*b2v;
                acc[3][0] += a.x*b3v; acc[3][1] += a.y*b3v;
            }
            __syncthreads();
        }
    }
#pragma unroll
    for (int mi = 0; mi < 2; mi++) {
        int m = mt * 2 + mi;
        int j = j0 + jt;
        float gi = acc[0][mi] + b2[j];
        float gf = acc[1][mi] + b2[1024 + j];
        float gg = acc[2][mi] + b2[2048 + j];
        float go = acc[3][mi] + b2[3072 + j];
        int idx = m * H + j;
        float cn = sigmoidf_(gf) * g_c2[idx] + sigmoidf_(gi) * tanhf(gg);
        g_c2[idx] = cn;
        float hv = sigmoidf_(go) * tanhf(cn);
        h2n[idx] = hv;
        g_lstm_out[((size_t)m * NT + t) * H + j] = hv + h1t[idx];
    }
}

// ---------------- K4: hid = relu(lstm_out @ Wp1 + bp1) -----------------------
// Wp1 is [1024][256] (n contiguous). Tile 64x64, grid (4,128).
__global__ __launch_bounds__(256) void k_mlp1(
    const float* __restrict__ Wp1, const float* __restrict__ bp1)
{
    __shared__ float As[16][64];
    __shared__ float Bs[16][64];
    const int bm = blockIdx.y * 64;
    const int bn = blockIdx.x * 64;
    const int tid = threadIdx.x;
    const int tm = (tid >> 4) * 4;
    const int tn = (tid & 15) * 4;
    const int lr = tid >> 2;
    const int lk = (tid & 3) * 4;
    const int kr = tid >> 4;           // B loader: k row 0..15
    const int ln = (tid & 15) * 4;     // B loader: n col
    float acc[4][4] = {};

    for (int k0 = 0; k0 < H; k0 += 16) {
        float4 av = *(const float4*)(g_lstm_out + (size_t)(bm + lr) * H + k0 + lk);
        As[lk+0][lr] = av.x; As[lk+1][lr] = av.y; As[lk+2][lr] = av.z; As[lk+3][lr] = av.w;
        float4 bv = *(const float4*)(Wp1 + (size_t)(k0 + kr) * NH1 + bn + ln);
        *(float4*)&Bs[kr][ln] = bv;
        __syncthreads();
#pragma unroll
        for (int kk = 0; kk < 16; kk++) {
            float4 a = *(const float4*)&As[kk][tm];
            float4 b = *(const float4*)&Bs[kk][tn];
            acc[0][0] += a.x*b.x; acc[0][1] += a.x*b.y; acc[0][2] += a.x*b.z; acc[0][3] += a.x*b.w;
            acc[1][0] += a.y*b.x; acc[1][1] += a.y*b.y; acc[1][2] += a.y*b.z; acc[1][3] += a.y*b.w;
            acc[2][0] += a.z*b.x; acc[2][1] += a.z*b.y; acc[2][2] += a.z*b.z; acc[2][3] += a.z*b.w;
            acc[3][0] += a.w*b.x; acc[3][1] += a.w*b.y; acc[3][2] += a.w*b.z; acc[3][3] += a.w*b.w;
        }
        __syncthreads();
    }
#pragma unroll
    for (int i = 0; i < 4; i++) {
#pragma unroll
        for (int j = 0; j < 4; j++) {
            float v = acc[i][j] + bp1[bn + tn + j];
            g_hid[(size_t)(bm + tm + i) * NH1 + bn + tn + j] = fmaxf(v, 0.f);
        }
    }
}

// ---------------- K5: logits = hid @ Wp2 + bp2 -> d_out ----------------------
// Wp2 is [256][1000] (n contiguous). Tile 64x64 with n<1000 guards, grid (16,128).
__global__ __launch_bounds__(256) void k_logits(
    const float* __restrict__ Wp2, const float* __restrict__ bp2,
    float* __restrict__ out)
{
    __shared__ float As[16][64];
    __shared__ float Bs[16][64];
    const int bm = blockIdx.y * 64;
    const int bn = blockIdx.x * 64;
    const int tid = threadIdx.x;
    const int tm = (tid >> 4) * 4;
    const int tn = (tid & 15) * 4;
    const int lr = tid >> 2;
    const int lk = (tid & 3) * 4;
    const int kr = tid >> 4;
    const int ln = (tid & 15) * 4;
    float acc[4][4] = {};

    for (int k0 = 0; k0 < NH1; k0 += 16) {
        float4 av = *(const float4*)(g_hid + (size_t)(bm + lr) * NH1 + k0 + lk);
        As[lk+0][lr] = av.x; As[lk+1][lr] = av.y; As[lk+2][lr] = av.z; As[lk+3][lr] = av.w;
#pragma unroll
        for (int i = 0; i < 4; i++) {
            int n = bn + ln + i;
            Bs[kr][ln + i] = (n < NANS) ? Wp2[(size_t)(k0 + kr) * NANS + n] : 0.f;
        }
        __syncthreads();
#pragma unroll
        for (int kk = 0; kk < 16; kk++) {
            float4 a = *(const float4*)&As[kk][tm];
            float4 b = *(const float4*)&Bs[kk][tn];
            acc[0][0] += a.x*b.x; acc[0][1] += a.x*b.y; acc[0][2] += a.x*b.z; acc[0][3] += a.x*b.w;
            acc[1][0] += a.y*b.x; acc[1][1] += a.y*b.y; acc[1][2] += a.y*b.z; acc[1][3] += a.y*b.w;
            acc[2][0] += a.z*b.x; acc[2][1] += a.z*b.y; acc[2][2] += a.z*b.z; acc[2][3] += a.z*b.w;
            acc[3][0] += a.w*b.x; acc[3][1] += a.w*b.y; acc[3][2] += a.w*b.z; acc[3][3] += a.w*b.w;
        }
        __syncthreads();
    }
#pragma unroll
    for (int i = 0; i < 4; i++) {
#pragma unroll
        for (int j = 0; j < 4; j++) {
            int n = bn + tn + j;
            if (n < NANS)
                out[(size_t)(bm + tm + i) * NANS + n] = acc[i][j] + bp2[n];
        }
    }
}

// ---------------- K6: in-place row softmax over 1000 -------------------------
__global__ __launch_bounds__(256) void k_softmax(float* __restrict__ out)
{
    __shared__ float red[256];
    const int tid = threadIdx.x;
    float* p = out + (size_t)blockIdx.x * NANS;
    float v[4];
    float mx = -1e30f;
#pragma unroll
    for (int i = 0; i < 4; i++) {
        int n = tid + i * 256;
        v[i] = (n < NANS) ? p[n] : -1e30f;
        mx = fmaxf(mx, v[i]);
    }
    red[tid] = mx; __syncthreads();
    for (int s = 128; s > 0; s >>= 1) {
        if (tid < s) red[tid] = fmaxf(red[tid], red[tid + s]);
        __syncthreads();
    }
    mx = red[0]; __syncthreads();
    float sum = 0.f;
#pragma unroll
    for (int i = 0; i < 4; i++) {
        int n = tid + i * 256;
        if (n < NANS) { v[i] = expf(v[i] - mx); sum += v[i]; }
    }
    red[tid] = sum; __syncthreads();
    for (int s = 128; s > 0; s >>= 1) {
        if (tid < s) red[tid] += red[tid + s];
        __syncthreads();
    }
    float inv = 1.f / red[0];
#pragma unroll
    for (int i = 0; i < 4; i++) {
        int n = tid + i * 256;
        if (n < NANS) p[n] = v[i] * inv;
    }
}

// ---------------- launch ------------------------------------------------------
extern "C" void kernel_launch(void* const* d_in, const int* in_sizes, int n_in,
                              void* d_out, int out_size)
{
    const float* data1 = (const float*)d_in[0];
    const float* data2 = (const float*)d_in[1];
    const float* W_ih1 = (const float*)d_in[2];
    const float* W_hh1 = (const float*)d_in[3];
    const float* b1    = (const float*)d_in[4];
    const float* W_ih2 = (const float*)d_in[5];
    const float* W_hh2 = (const float*)d_in[6];
    const float* b2    = (const float*)d_in[7];
    const float* Wp1   = (const float*)d_in[8];
    const float* bp1   = (const float*)d_in[9];
    const float* Wp2   = (const float*)d_in[10];
    const float* bp2   = (const float*)d_in[11];
    float* out = (float*)d_out;

    k_init_state<<<256, 256>>>();
    k_xproj<<<dim3(64, 128), 256>>>(data1, data2, W_ih1, b1);
    for (int t = 0; t < NT; t++) {
        k_lstm1<<<128, 256>>>(W_hh1, t);
        k_lstm2<<<128, 256>>>(W_ih2, W_hh2, b2, t);
    }
    k_mlp1<<<dim3(4, 128), 256>>>(Wp1, bp1);
    k_logits<<<dim3(16, 128), 256>>>(Wp2, bp2, out);
    k_softmax<<<BT, 256>>>(out);
}

// round 2
// speedup vs baseline: 2.7449x; 2.7449x over previous
#include <cuda_runtime.h>
#include <cstdint>
#include <math.h>

// Problem dims
#define NB   64      // batch
#define NT   128     // time
#define BT   8192    // NB*NT
#define H    1024    // hidden
#define DIN  2048    // dim1+dim2
#define G4   4096    // 4*H
#define NH1  256     // H/4 (MLP hidden)
#define NANS 1000

// ---------------- device scratch (static device globals: no allocation) ----
__device__ float g_X1[(size_t)BT * G4];        // input projection, t-major: [t][b][4H]
__device__ float g_h1[2][NB * H];              // ping-pong
__device__ float g_c1[NB * H];
__device__ float g_h2[2][NB * H];
__device__ float g_c2[NB * H];
__device__ float g_lstm_out[(size_t)BT * H];   // [b*NT + t][H]
__device__ float g_hid[(size_t)BT * NH1];

__device__ __forceinline__ float sigmoidf_(float x) { return 1.f / (1.f + expf(-x)); }

// tf32 convert (round-to-nearest)
__device__ __forceinline__ uint32_t f2tf(float f) {
    uint32_t u;
    asm("cvt.rna.tf32.f32 %0, %1;" : "=r"(u) : "f"(f));
    return u;
}
// m16n8k8 tf32 mma, fp32 accumulate
__device__ __forceinline__ void mma8(float c[4], const uint32_t a[4], const uint32_t b[2]) {
    asm volatile(
        "mma.sync.aligned.m16n8k8.row.col.f32.tf32.tf32.f32 "
        "{%0,%1,%2,%3},{%4,%5,%6,%7},{%8,%9},{%0,%1,%2,%3};"
        : "+f"(c[0]), "+f"(c[1]), "+f"(c[2]), "+f"(c[3])
        : "r"(a[0]), "r"(a[1]), "r"(a[2]), "r"(a[3]), "r"(b[0]), "r"(b[1]));
}
__device__ __forceinline__ void cp16(void* smem, const void* g) {
    uint32_t s = (uint32_t)__cvta_generic_to_shared(smem);
    asm volatile("cp.async.cg.shared.global [%0], [%1], 16;" :: "r"(s), "l"(g));
}
__device__ __forceinline__ void cp_commit() { asm volatile("cp.async.commit_group;"); }
__device__ __forceinline__ void cp_wait1()  { asm volatile("cp.async.wait_group 1;"); }
__device__ __forceinline__ void cp_wait0()  { asm volatile("cp.async.wait_group 0;"); }

// ---------------- state init (re-runs every launch for graph replay) -------
__global__ void k_init_state() {
    int i = blockIdx.x * blockDim.x + threadIdx.x;
    if (i < NB * H) {
        g_h1[0][i] = 0.f; g_h2[0][i] = 0.f;
        g_c1[i]    = 0.f; g_c2[i]    = 0.f;
    }
}

// =================== K1: X1 = [d1|d2] @ W_ih1^T + b1 (tf32 mma) =============
// C[8192][4096]. CTA tile 64x64, K_BLK=32, double-buffered cp.async.
// Output remapped m=b*128+t -> [t][b] so each step reads a contiguous slab.
__global__ __launch_bounds__(256) void k_xproj(
    const float* __restrict__ d1, const float* __restrict__ d2,
    const float* __restrict__ W, const float* __restrict__ bias)
{
    __shared__ float As[2][64][36];
    __shared__ float Bs[2][64][36];
    const int bm = blockIdx.y * 64;
    const int bn = blockIdx.x * 64;
    const int tid  = threadIdx.x;
    const int wid  = tid >> 5, lane = tid & 31;
    const int wm   = (wid & 3) * 16;       // warp row base
    const int wn   = (wid >> 2) * 32;      // warp col base
    const int rr   = lane >> 2, cc = lane & 3;
    float acc[4][4] = {};

    const int NIT = DIN / 32;  // 64

    auto load = [&](int it) {
        int st = it & 1;
        int k0 = it * 32;
#pragma unroll
        for (int e = 0; e < 2; e++) {
            int i = tid * 2 + e;            // 0..511
            int row = i >> 3, c4 = (i & 7) * 4;
            int gm = bm + row;
            const float* src = (k0 < 1024)
                ? (d1 + (size_t)gm * 1024 + k0 + c4)
                : (d2 + (size_t)gm * 1024 + (k0 - 1024) + c4);
            cp16(&As[st][row][c4], src);
            cp16(&Bs[st][row][c4], W + (size_t)(bn + row) * DIN + k0 + c4);
        }
    };

    load(0); cp_commit();
    for (int it = 0; it < NIT; it++) {
        int st = it & 1;
        if (it + 1 < NIT) { load(it + 1); cp_commit(); cp_wait1(); }
        else { cp_wait0(); }
        __syncthreads();
#pragma unroll
        for (int kk = 0; kk < 32; kk += 8) {
            uint32_t a[4];
            a[0] = f2tf(As[st][wm + rr    ][kk + cc    ]);
            a[1] = f2tf(As[st][wm + rr + 8][kk + cc    ]);
            a[2] = f2tf(As[st][wm + rr    ][kk + cc + 4]);
            a[3] = f2tf(As[st][wm + rr + 8][kk + cc + 4]);
#pragma unroll
            for (int j = 0; j < 4; j++) {
                uint32_t b[2];
                b[0] = f2tf(Bs[st][wn + j * 8 + rr][kk + cc    ]);
                b[1] = f2tf(Bs[st][wn + j * 8 + rr][kk + cc + 4]);
                mma8(acc[j], a, b);
            }
        }
        __syncthreads();
    }
    // epilogue: remap + bias
#pragma unroll
    for (int j = 0; j < 4; j++) {
        int col = bn + wn + j * 8 + cc * 2;
#pragma unroll
        for (int h = 0; h < 2; h++) {      // h: row +0 / +8
            int m = bm + wm + rr + h * 8;
            int t  = m & (NT - 1);
            int bb = m >> 7;
            float* orow = g_X1 + ((size_t)t * NB + bb) * G4 + col;
            orow[0] = acc[j][h * 2 + 0] + bias[col];
            orow[1] = acc[j][h * 2 + 1] + bias[col + 1];
        }
    }
}

// =================== K2/K3: LSTM step (tf32 mma, fused cell) ================
// gates[64][32] for j-block of 8 across all 4 gates.
// L1: gates = h1_prev @ Whh1^T + X1[t]       (K=1024)
// L2: gates = h1_t @ Wih2^T + h2_prev @ Whh2^T + b2, residual out (K=2048)
template<bool L2>
__global__ __launch_bounds__(256) void k_step(
    int t, const float* __restrict__ Wa, const float* __restrict__ Wb,
    const float* __restrict__ bias)
{
    __shared__ float As[2][64][36];
    __shared__ float Bs[2][32][36];
    __shared__ float Gs[64][33];

    const int j0  = blockIdx.x * 8;
    const int tid = threadIdx.x;
    const int wid = tid >> 5, lane = tid & 31;
    const int wm  = (wid & 3) * 16;
    const int wn  = (wid >> 2) * 16;
    const int rr  = lane >> 2, cc = lane & 3;
    float acc[2][4] = {};

    const float* h1_in = g_h1[t & 1];
    float*       h1_out = g_h1[(t + 1) & 1];
    const float* h1t = g_h1[(t + 1) & 1];   // L2 input (written by L1 at this t)
    const float* h2p = g_h2[t & 1];
    float*       h2n = g_h2[(t + 1) & 1];

    const int NIT = L2 ? 64 : 32;

    auto load = [&](int it) {
        int st = it & 1;
        int p  = it >> 5;                   // pair select (0 for L1)
        int k0 = (it & 31) * 32;
        const float* Asrc = L2 ? (p == 0 ? h1t : h2p) : h1_in;
        const float* Wsel = (p == 0) ? Wa : Wb;
        // A: 64 rows x 8 float4 = 512 -> 2/thread
#pragma unroll
        for (int e = 0; e < 2; e++) {
            int i = tid * 2 + e;
            int row = i >> 3, c4 = (i & 7) * 4;
            cp16(&As[st][row][c4], Asrc + (size_t)row * H + k0 + c4);
        }
        // B: 32 rows (4 gates x 8 j) x 8 float4 = 256 -> 1/thread
        {
            int row = tid >> 3, c4 = (tid & 7) * 4;
            int g = row >> 3, jj = row & 7;
            cp16(&Bs[st][row][c4], Wsel + (size_t)(g * H + j0 + jj) * H + k0 + c4);
        }
    };

    load(0); cp_commit();
    for (int it = 0; it < NIT; it++) {
        int st = it & 1;
        if (it + 1 < NIT) { load(it + 1); cp_commit(); cp_wait1(); }
        else { cp_wait0(); }
        __syncthreads();
#pragma unroll
        for (int kk = 0; kk < 32; kk += 8) {
            uint32_t a[4];
            a[0] = f2tf(As[st][wm + rr    ][kk + cc    ]);
            a[1] = f2tf(As[st][wm + rr + 8][kk + cc    ]);
            a[2] = f2tf(As[st][wm + rr    ][kk + cc + 4]);
            a[3] = f2tf(As[st][wm + rr + 8][kk + cc + 4]);
#pragma unroll
            for (int j = 0; j < 2; j++) {
                uint32_t b[2];
                b[0] = f2tf(Bs[st][wn + j * 8 + rr][kk + cc    ]);
                b[1] = f2tf(Bs[st][wn + j * 8 + rr][kk + cc + 4]);
                mma8(acc[j], a, b);
            }
        }
        __syncthreads();
    }

    // stage gates to smem (cross-warp: cell needs all 4 gates per (m,j))
#pragma unroll
    for (int j = 0; j < 2; j++) {
        int c = wn + j * 8 + cc * 2;
        Gs[wm + rr    ][c    ] = acc[j][0];
        Gs[wm + rr    ][c + 1] = acc[j][1];
        Gs[wm + rr + 8][c    ] = acc[j][2];
        Gs[wm + rr + 8][c + 1] = acc[j][3];
    }
    __syncthreads();

    const float* Xt = g_X1 + (size_t)t * NB * G4;
#pragma unroll
    for (int e = 0; e < 2; e++) {
        int idx = tid * 2 + e;              // 0..511
        int m = idx >> 3, jj = idx & 7;
        int j = j0 + jj;
        float gi = Gs[m][jj], gf = Gs[m][8 + jj], gg = Gs[m][16 + jj], go = Gs[m][24 + jj];
        int hidx = m * H + j;
        if (!L2) {
            const float* xr = Xt + (size_t)m * G4 + j;  // contains +b1
            gi += xr[0]; gf += xr[1024]; gg += xr[2048]; go += xr[3072];
            float cn = sigmoidf_(gf) * g_c1[hidx] + sigmoidf_(gi) * tanhf(gg);
            g_c1[hidx]  = cn;
            h1_out[hidx] = sigmoidf_(go) * tanhf(cn);
        } else {
            gi += bias[j]; gf += bias[1024 + j]; gg += bias[2048 + j]; go += bias[3072 + j];
            float cn = sigmoidf_(gf) * g_c2[hidx] + sigmoidf_(gi) * tanhf(gg);
            g_c2[hidx] = cn;
            float hv = sigmoidf_(go) * tanhf(cn);
            h2n[hidx] = hv;
            g_lstm_out[((size_t)m * NT + t) * H + j] = hv + h1t[hidx];
        }
    }
}

// ---------------- K4: hid = relu(lstm_out @ Wp1 + bp1) (fp32) ---------------
__global__ __launch_bounds__(256) void k_mlp1(
    const float* __restrict__ Wp1, const float* __restrict__ bp1)
{
    __shared__ float As[16][64];
    __shared__ float Bs[16][64];
    const int bm = blockIdx.y * 64;
    const int bn = blockIdx.x * 64;
    const int tid = threadIdx.x;
    const int tm = (tid >> 4) * 4;
    const int tn = (tid & 15) * 4;
    const int lr = tid >> 2;
    const int lk = (tid & 3) * 4;
    const int kr = tid >> 4;
    const int ln = (tid & 15) * 4;
    float acc[4][4] = {};

    for (int k0 = 0; k0 < H; k0 += 16) {
        float4 av = *(const float4*)(g_lstm_out + (size_t)(bm + lr) * H + k0 + lk);
        As[lk+0][lr] = av.x; As[lk+1][lr] = av.y; As[lk+2][lr] = av.z; As[lk+3][lr] = av.w;
        float4 bv = *(const float4*)(Wp1 + (size_t)(k0 + kr) * NH1 + bn + ln);
        *(float4*)&Bs[kr][ln] = bv;
        __syncthreads();
#pragma unroll
        for (int kk = 0; kk < 16; kk++) {
            float4 a = *(const float4*)&As[kk][tm];
            float4 b = *(const float4*)&Bs[kk][tn];
            acc[0][0] += a.x*b.x; acc[0][1] += a.x*b.y; acc[0][2] += a.x*b.z; acc[0][3] += a.x*b.w;
            acc[1][0] += a.y*b.x; acc[1][1] += a.y*b.y; acc[1][2] += a.y*b.z; acc[1][3] += a.y*b.w;
            acc[2][0] += a.z*b.x; acc[2][1] += a.z*b.y; acc[2][2] += a.z*b.z; acc[2][3] += a.z*b.w;
            acc[3][0] += a.w*b.x; acc[3][1] += a.w*b.y; acc[3][2] += a.w*b.z; acc[3][3] += a.w*b.w;
        }
        __syncthreads();
    }
#pragma unroll
    for (int i = 0; i < 4; i++)
#pragma unroll
        for (int j = 0; j < 4; j++) {
            float v = acc[i][j] + bp1[bn + tn + j];
            g_hid[(size_t)(bm + tm + i) * NH1 + bn + tn + j] = fmaxf(v, 0.f);
        }
}

// ---------------- K5: logits = hid @ Wp2 + bp2 -> d_out (fp32) --------------
__global__ __launch_bounds__(256) void k_logits(
    const float* __restrict__ Wp2, const float* __restrict__ bp2,
    float* __restrict__ out)
{
    __shared__ float As[16][64];
    __shared__ float Bs[16][64];
    const int bm = blockIdx.y * 64;
    const int bn = blockIdx.x * 64;
    const int tid = threadIdx.x;
    const int tm = (tid >> 4) * 4;
    const int tn = (tid & 15) * 4;
    const int lr = tid >> 2;
    const int lk = (tid & 3) * 4;
    const int kr = tid >> 4;
    const int ln = (tid & 15) * 4;
    float acc[4][4] = {};

    for (int k0 = 0; k0 < NH1; k0 += 16) {
        float4 av = *(const float4*)(g_hid + (size_t)(bm + lr) * NH1 + k0 + lk);
        As[lk+0][lr] = av.x; As[lk+1][lr] = av.y; As[lk+2][lr] = av.z; As[lk+3][lr] = av.w;
#pragma unroll
        for (int i = 0; i < 4; i++) {
            int n = bn + ln + i;
            Bs[kr][ln + i] = (n < NANS) ? Wp2[(size_t)(k0 + kr) * NANS + n] : 0.f;
        }
        __syncthreads();
#pragma unroll
        for (int kk = 0; kk < 16; kk++) {
            float4 a = *(const float4*)&As[kk][tm];
            float4 b = *(const float4*)&Bs[kk][tn];
            acc[0][0] += a.x*b.x; acc[0][1] += a.x*b.y; acc[0][2] += a.x*b.z; acc[0][3] += a.x*b.w;
            acc[1][0] += a.y*b.x; acc[1][1] += a.y*b.y; acc[1][2] += a.y*b.z; acc[1][3] += a.y*b.w;
            acc[2][0] += a.z*b.x; acc[2][1] += a.z*b.y; acc[2][2] += a.z*b.z; acc[2][3] += a.z*b.w;
            acc[3][0] += a.w*b.x; acc[3][1] += a.w*b.y; acc[3][2] += a.w*b.z; acc[3][3] += a.w*b.w;
        }
        __syncthreads();
    }
#pragma unroll
    for (int i = 0; i < 4; i++)
#pragma unroll
        for (int j = 0; j < 4; j++) {
            int n = bn + tn + j;
            if (n < NANS)
                out[(size_t)(bm + tm + i) * NANS + n] = acc[i][j] + bp2[n];
        }
}

// ---------------- K6: in-place row softmax over 1000 -------------------------
__global__ __launch_bounds__(256) void k_softmax(float* __restrict__ out)
{
    __shared__ float red[256];
    const int tid = threadIdx.x;
    float* p = out + (size_t)blockIdx.x * NANS;
    float v[4];
    float mx = -1e30f;
#pragma unroll
    for (int i = 0; i < 4; i++) {
        int n = tid + i * 256;
        v[i] = (n < NANS) ? p[n] : -1e30f;
        mx = fmaxf(mx, v[i]);
    }
    red[tid] = mx; __syncthreads();
    for (int s = 128; s > 0; s >>= 1) {
        if (tid < s) red[tid] = fmaxf(red[tid], red[tid + s]);
        __syncthreads();
    }
    mx = red[0]; __syncthreads();
    float sum = 0.f;
#pragma unroll
    for (int i = 0; i < 4; i++) {
        int n = tid + i * 256;
        if (n < NANS) { v[i] = expf(v[i] - mx); sum += v[i]; }
    }
    red[tid] = sum; __syncthreads();
    for (int s = 128; s > 0; s >>= 1) {
        if (tid < s) red[tid] += red[tid + s];
        __syncthreads();
    }
    float inv = 1.f / red[0];
#pragma unroll
    for (int i = 0; i < 4; i++) {
        int n = tid + i * 256;
        if (n < NANS) p[n] = v[i] * inv;
    }
}

// ---------------- launch ------------------------------------------------------
extern "C" void kernel_launch(void* const* d_in, const int* in_sizes, int n_in,
                              void* d_out, int out_size)
{
    const float* data1 = (const float*)d_in[0];
    const float* data2 = (const float*)d_in[1];
    const float* W_ih1 = (const float*)d_in[2];
    const float* W_hh1 = (const float*)d_in[3];
    const float* b1    = (const float*)d_in[4];
    const float* W_ih2 = (const float*)d_in[5];
    const float* W_hh2 = (const float*)d_in[6];
    const float* b2    = (const float*)d_in[7];
    const float* Wp1   = (const float*)d_in[8];
    const float* bp1   = (const float*)d_in[9];
    const float* Wp2   = (const float*)d_in[10];
    const float* bp2   = (const float*)d_in[11];
    float* out = (float*)d_out;

    k_init_state<<<256, 256>>>();
    k_xproj<<<dim3(64, 128), 256>>>(data1, data2, W_ih1, b1);
    for (int t = 0; t < NT; t++) {
        k_step<false><<<128, 256>>>(t, W_hh1, nullptr, nullptr);
        k_step<true ><<<128, 256>>>(t, W_ih2, W_hh2, b2);
    }
    k_mlp1<<<dim3(4, 128), 256>>>(Wp1, bp1);
    k_logits<<<dim3(16, 128), 256>>>(Wp2, bp2, out);
    k_softmax<<<BT, 256>>>(out);
}

// round 3
// speedup vs baseline: 4.7984x; 1.7481x over previous
#include <cuda_runtime.h>
#include <cuda_bf16.h>
#include <cstdint>
#include <math.h>

// Problem dims
#define NB   64
#define NT   128
#define BT   8192
#define H    1024
#define DIN  2048
#define G4   4096
#define NH1  256
#define NANS 1000

// ---------------- device scratch ----------------
__device__ float g_X1[(size_t)BT * G4];          // [t][b][4H], includes +b1
__device__ float g_lstm_out[(size_t)BT * H];     // [b*NT+t][H]
__device__ float g_hid[(size_t)BT * NH1];
__device__ float g_h1f[NB * H];                  // fp32 h1_t (for residual)
__device__ float g_c1[NB * H];
__device__ float g_c2[NB * H];
// bf16 fragment-packed buffers (aligned for uint4 access)
// h pack layout: [kc(64)][mt(4)][lane(32)][areg(4)] u32  -> 32768 u32 = 128KB
__device__ __align__(16) uint32_t g_h1p[2][32768];
__device__ __align__(16) uint32_t g_h2p[2][32768];
// W pack layout: [nb(64)][kc][c(8)][lane(32)][2] u32
__device__ __align__(16) uint32_t g_W1p[64 * 64 * 8 * 64];    // 2M u32
__device__ __align__(16) uint32_t g_W2p[64 * 128 * 8 * 64];   // 4M u32

__device__ __forceinline__ float sigmoidf_(float x) { return 1.f / (1.f + expf(-x)); }

__device__ __forceinline__ uint32_t pk(float x, float y) {
    __nv_bfloat162 v = __floats2bfloat162_rn(x, y);
    return *reinterpret_cast<uint32_t*>(&v);
}
// tf32 helpers (xproj)
__device__ __forceinline__ uint32_t f2tf(float f) {
    uint32_t u; asm("cvt.rna.tf32.f32 %0, %1;" : "=r"(u) : "f"(f)); return u;
}
__device__ __forceinline__ void mma8(float c[4], const uint32_t a[4], const uint32_t b[2]) {
    asm volatile(
        "mma.sync.aligned.m16n8k8.row.col.f32.tf32.tf32.f32 "
        "{%0,%1,%2,%3},{%4,%5,%6,%7},{%8,%9},{%0,%1,%2,%3};"
        : "+f"(c[0]), "+f"(c[1]), "+f"(c[2]), "+f"(c[3])
        : "r"(a[0]), "r"(a[1]), "r"(a[2]), "r"(a[3]), "r"(b[0]), "r"(b[1]));
}
// bf16 m16n8k16 mma
__device__ __forceinline__ void mmabf(float c[4], uint4 a, uint2 b) {
    asm volatile(
        "mma.sync.aligned.m16n8k16.row.col.f32.bf16.bf16.f32 "
        "{%0,%1,%2,%3},{%4,%5,%6,%7},{%8,%9},{%0,%1,%2,%3};"
        : "+f"(c[0]), "+f"(c[1]), "+f"(c[2]), "+f"(c[3])
        : "r"(a.x), "r"(a.y), "r"(a.z), "r"(a.w), "r"(b.x), "r"(b.y));
}
__device__ __forceinline__ void cp16(void* smem, const void* g) {
    uint32_t s = (uint32_t)__cvta_generic_to_shared(smem);
    asm volatile("cp.async.cg.shared.global [%0], [%1], 16;" :: "r"(s), "l"(g));
}
__device__ __forceinline__ void cp_commit() { asm volatile("cp.async.commit_group;"); }
__device__ __forceinline__ void cp_wait2()  { asm volatile("cp.async.wait_group 2;"); }
__device__ __forceinline__ void cp_wait1()  { asm volatile("cp.async.wait_group 1;"); }
__device__ __forceinline__ void cp_wait0()  { asm volatile("cp.async.wait_group 0;"); }

// ---------------- state init (re-runs every launch) -------------------------
__global__ void k_init_state() {
    int i = blockIdx.x * blockDim.x + threadIdx.x;
    if (i < NB * H) { g_c1[i] = 0.f; g_c2[i] = 0.f; g_h1f[i] = 0.f; }
    if (i < 32768)  { g_h1p[0][i] = 0u; g_h2p[0][i] = 0u; }
}

// ---------------- weight pack: fp32 [4H][H] -> bf16 B-fragments --------------
// chunk c = s*4+g ; row = g*H + nb*16 + s*8 + rr ; per (nb,kc,c,lane): b0,b1
__global__ void k_pack_w(const float* __restrict__ Wa, const float* __restrict__ Wb,
                         int nkc, uint32_t* __restrict__ out)
{
    int total = 64 * nkc * 8 * 32;
    for (int idx = blockIdx.x * blockDim.x + threadIdx.x; idx < total;
         idx += gridDim.x * blockDim.x) {
        int lane = idx & 31;
        int t2 = idx >> 5;  int c  = t2 & 7;
        int t3 = t2 >> 3;   int kc = t3 % nkc; int nb = t3 / nkc;
        int g = c & 3, s = c >> 2;
        int rr = lane >> 2, cc2 = (lane & 3) * 2;
        int row = g * H + nb * 16 + s * 8 + rr;
        const float* W = Wa; int kk = kc * 16;
        if (kc >= 64) { W = Wb; kk = (kc - 64) * 16; }
        const float* p = W + (size_t)row * H + kk + cc2;
        out[idx * 2 + 0] = pk(p[0], p[1]);
        out[idx * 2 + 1] = pk(p[8], p[9]);
    }
}

// =================== K1: X1 = [d1|d2] @ W_ih1^T + b1 (tf32 mma) =============
__global__ __launch_bounds__(256) void k_xproj(
    const float* __restrict__ d1, const float* __restrict__ d2,
    const float* __restrict__ W, const float* __restrict__ bias)
{
    __shared__ float As[2][64][36];
    __shared__ float Bs[2][64][36];
    const int bm = blockIdx.y * 64;
    const int bn = blockIdx.x * 64;
    const int tid  = threadIdx.x;
    const int wid  = tid >> 5, lane = tid & 31;
    const int wm   = (wid & 3) * 16;
    const int wn   = (wid >> 2) * 32;
    const int rr   = lane >> 2, cc = lane & 3;
    float acc[4][4] = {};
    const int NIT = DIN / 32;

    auto load = [&](int it) {
        int st = it & 1;
        int k0 = it * 32;
#pragma unroll
        for (int e = 0; e < 2; e++) {
            int i = tid * 2 + e;
            int row = i >> 3, c4 = (i & 7) * 4;
            int gm = bm + row;
            const float* src = (k0 < 1024)
                ? (d1 + (size_t)gm * 1024 + k0 + c4)
                : (d2 + (size_t)gm * 1024 + (k0 - 1024) + c4);
            cp16(&As[st][row][c4], src);
            cp16(&Bs[st][row][c4], W + (size_t)(bn + row) * DIN + k0 + c4);
        }
    };

    load(0); cp_commit();
    for (int it = 0; it < NIT; it++) {
        int st = it & 1;
        if (it + 1 < NIT) { load(it + 1); cp_commit(); cp_wait1(); }
        else { cp_wait0(); }
        __syncthreads();
#pragma unroll
        for (int kk = 0; kk < 32; kk += 8) {
            uint32_t a[4];
            a[0] = f2tf(As[st][wm + rr    ][kk + cc    ]);
            a[1] = f2tf(As[st][wm + rr + 8][kk + cc    ]);
            a[2] = f2tf(As[st][wm + rr    ][kk + cc + 4]);
            a[3] = f2tf(As[st][wm + rr + 8][kk + cc + 4]);
#pragma unroll
            for (int j = 0; j < 4; j++) {
                uint32_t b[2];
                b[0] = f2tf(Bs[st][wn + j * 8 + rr][kk + cc    ]);
                b[1] = f2tf(Bs[st][wn + j * 8 + rr][kk + cc + 4]);
                mma8(acc[j], a, b);
            }
        }
        __syncthreads();
    }
#pragma unroll
    for (int j = 0; j < 4; j++) {
        int col = bn + wn + j * 8 + cc * 2;
#pragma unroll
        for (int h = 0; h < 2; h++) {
            int m = bm + wm + rr + h * 8;
            int t  = m & (NT - 1);
            int bb = m >> 7;
            float* orow = g_X1 + ((size_t)t * NB + bb) * G4 + col;
            orow[0] = acc[j][h * 2 + 0] + bias[col];
            orow[1] = acc[j][h * 2 + 1] + bias[col + 1];
        }
    }
}

// =================== LSTM step: bf16 fragment GEMM + fused cell =============
// grid 64 (j-blocks of 16), 256 thr. Warp (mt=wid&3, s=wid>>2).
// acc[g][r]: C rows mt*16+rr(+8), cols j = bx*16 + s*8 + 2cc (+1), gate g.
// Stage = 4 kc-chunks of k16: A 8KB + B 8KB = 16KB; 4 stages dynamic smem.
template<bool IS_L2>
__global__ __launch_bounds__(256) void k_stepb(int t, const float* __restrict__ bias)
{
    extern __shared__ uint4 sm[];
    const int tid = threadIdx.x, wid = tid >> 5, lane = tid & 31;
    const int mt = wid & 3, s = wid >> 2;
    const int rr = lane >> 2, cc = lane & 3;
    const int bx = blockIdx.x;
    const int NIT = IS_L2 ? 32 : 16;
    const int nkc = IS_L2 ? 128 : 64;
    const uint32_t* Wp = IS_L2 ? g_W2p : g_W1p;
    const uint32_t* h1prev = g_h1p[t & 1];
    const uint32_t* h1cur  = g_h1p[(t + 1) & 1];   // written by L1 at this t
    const uint32_t* h2prev = g_h2p[t & 1];
    float acc[4][4] = {};

    auto load = [&](int it) {
        if (it >= NIT) return;
        uint4* dst = sm + (it & 3) * 1024;
        const uint32_t* asrc;
        if (!IS_L2) asrc = h1prev + it * 2048;
        else        asrc = (it < 16) ? (h1cur + it * 2048) : (h2prev + (it - 16) * 2048);
        const uint4* a4 = (const uint4*)asrc;
        const uint4* b4 = (const uint4*)(Wp + ((size_t)bx * nkc + it * 4) * 512);
        cp16(&dst[tid],           &a4[tid]);
        cp16(&dst[tid + 256],     &a4[tid + 256]);
        cp16(&dst[512 + tid],     &b4[tid]);
        cp16(&dst[512 + tid + 256], &b4[tid + 256]);
    };

    load(0); cp_commit();
    load(1); cp_commit();
    load(2); cp_commit();
    for (int it = 0; it < NIT; it++) {
        cp_wait2();
        __syncthreads();
        const uint4* SA = sm + (it & 3) * 1024;
        const uint2* SB = (const uint2*)(SA + 512);
#pragma unroll
        for (int k4 = 0; k4 < 4; k4++) {
            uint4 a = SA[(k4 * 4 + mt) * 32 + lane];
#pragma unroll
            for (int g = 0; g < 4; g++) {
                uint2 b = SB[(size_t)((k4 * 8 + s * 4 + g) * 32 + lane)];
                mmabf(acc[g], a, b);
            }
        }
        load(it + 3); cp_commit();
    }

    // fused cell epilogue (register-local: thread owns all 4 gates of its (m,j))
    const int j = (bx << 4) + (s << 3) + (cc << 1);
    const float* Xt = g_X1 + (size_t)t * NB * G4;
#pragma unroll
    for (int hh = 0; hh < 2; hh++) {
        const int m = mt * 16 + rr + hh * 8;
        float gi0 = acc[0][hh*2], gi1 = acc[0][hh*2+1];
        float gf0 = acc[1][hh*2], gf1 = acc[1][hh*2+1];
        float gg0 = acc[2][hh*2], gg1 = acc[2][hh*2+1];
        float go0 = acc[3][hh*2], go1 = acc[3][hh*2+1];
        const uint32_t pidx = (uint32_t)(((bx * 4 + mt) * 32 + lane) * 4 + s * 2 + hh);
        if (!IS_L2) {
            const float* xr = Xt + (size_t)m * G4 + j;
            float2 xi = *(const float2*)(xr);
            float2 xf = *(const float2*)(xr + H);
            float2 xg = *(const float2*)(xr + 2 * H);
            float2 xo = *(const float2*)(xr + 3 * H);
            gi0 += xi.x; gi1 += xi.y; gf0 += xf.x; gf1 += xf.y;
            gg0 += xg.x; gg1 += xg.y; go0 += xo.x; go1 += xo.y;
            float2 cp = *(const float2*)&g_c1[m * H + j];
            float cn0 = sigmoidf_(gf0) * cp.x + sigmoidf_(gi0) * tanhf(gg0);
            float cn1 = sigmoidf_(gf1) * cp.y + sigmoidf_(gi1) * tanhf(gg1);
            *(float2*)&g_c1[m * H + j] = make_float2(cn0, cn1);
            float h0 = sigmoidf_(go0) * tanhf(cn0);
            float h1 = sigmoidf_(go1) * tanhf(cn1);
            *(float2*)&g_h1f[m * H + j] = make_float2(h0, h1);
            g_h1p[(t + 1) & 1][pidx] = pk(h0, h1);
        } else {
            gi0 += bias[j];         gi1 += bias[j + 1];
            gf0 += bias[H + j];     gf1 += bias[H + j + 1];
            gg0 += bias[2*H + j];   gg1 += bias[2*H + j + 1];
            go0 += bias[3*H + j];   go1 += bias[3*H + j + 1];
            float2 cp = *(const float2*)&g_c2[m * H + j];
            float cn0 = sigmoidf_(gf0) * cp.x + sigmoidf_(gi0) * tanhf(gg0);
            float cn1 = sigmoidf_(gf1) * cp.y + sigmoidf_(gi1) * tanhf(gg1);
            *(float2*)&g_c2[m * H + j] = make_float2(cn0, cn1);
            float h0 = sigmoidf_(go0) * tanhf(cn0);
            float h1 = sigmoidf_(go1) * tanhf(cn1);
            g_h2p[(t + 1) & 1][pidx] = pk(h0, h1);
            float2 r1 = *(const float2*)&g_h1f[m * H + j];
            *(float2*)&g_lstm_out[((size_t)m * NT + t) * H + j] =
                make_float2(h0 + r1.x, h1 + r1.y);
        }
    }
}

// ---------------- K4: hid = relu(lstm_out @ Wp1 + bp1) (fp32) ---------------
__global__ __launch_bounds__(256) void k_mlp1(
    const float* __restrict__ Wp1, const float* __restrict__ bp1)
{
    __shared__ float As[16][64];
    __shared__ float Bs[16][64];
    const int bm = blockIdx.y * 64;
    const int bn = blockIdx.x * 64;
    const int tid = threadIdx.x;
    const int tm = (tid >> 4) * 4;
    const int tn = (tid & 15) * 4;
    const int lr = tid >> 2;
    const int lk = (tid & 3) * 4;
    const int kr = tid >> 4;
    const int ln = (tid & 15) * 4;
    float acc[4][4] = {};

    for (int k0 = 0; k0 < H; k0 += 16) {
        float4 av = *(const float4*)(g_lstm_out + (size_t)(bm + lr) * H + k0 + lk);
        As[lk+0][lr] = av.x; As[lk+1][lr] = av.y; As[lk+2][lr] = av.z; As[lk+3][lr] = av.w;
        float4 bv = *(const float4*)(Wp1 + (size_t)(k0 + kr) * NH1 + bn + ln);
        *(float4*)&Bs[kr][ln] = bv;
        __syncthreads();
#pragma unroll
        for (int kk = 0; kk < 16; kk++) {
            float4 a = *(const float4*)&As[kk][tm];
            float4 b = *(const float4*)&Bs[kk][tn];
            acc[0][0] += a.x*b.x; acc[0][1] += a.x*b.y; acc[0][2] += a.x*b.z; acc[0][3] += a.x*b.w;
            acc[1][0] += a.y*b.x; acc[1][1] += a.y*b.y; acc[1][2] += a.y*b.z; acc[1][3] += a.y*b.w;
            acc[2][0] += a.z*b.x; acc[2][1] += a.z*b.y; acc[2][2] += a.z*b.z; acc[2][3] += a.z*b.w;
            acc[3][0] += a.w*b.x; acc[3][1] += a.w*b.y; acc[3][2] += a.w*b.z; acc[3][3] += a.w*b.w;
        }
        __syncthreads();
    }
#pragma unroll
    for (int i = 0; i < 4; i++)
#pragma unroll
        for (int j = 0; j < 4; j++) {
            float v = acc[i][j] + bp1[bn + tn + j];
            g_hid[(size_t)(bm + tm + i) * NH1 + bn + tn + j] = fmaxf(v, 0.f);
        }
}

// ---------------- K5: logits = hid @ Wp2 + bp2 -> d_out (fp32) --------------
__global__ __launch_bounds__(256) void k_logits(
    const float* __restrict__ Wp2, const float* __restrict__ bp2,
    float* __restrict__ out)
{
    __shared__ float As[16][64];
    __shared__ float Bs[16][64];
    const int bm = blockIdx.y * 64;
    const int bn = blockIdx.x * 64;
    const int tid = threadIdx.x;
    const int tm = (tid >> 4) * 4;
    const int tn = (tid & 15) * 4;
    const int lr = tid >> 2;
    const int lk = (tid & 3) * 4;
    const int kr = tid >> 4;
    const int ln = (tid & 15) * 4;
    float acc[4][4] = {};

    for (int k0 = 0; k0 < NH1; k0 += 16) {
        float4 av = *(const float4*)(g_hid + (size_t)(bm + lr) * NH1 + k0 + lk);
        As[lk+0][lr] = av.x; As[lk+1][lr] = av.y; As[lk+2][lr] = av.z; As[lk+3][lr] = av.w;
#pragma unroll
        for (int i = 0; i < 4; i++) {
            int n = bn + ln + i;
            Bs[kr][ln + i] = (n < NANS) ? Wp2[(size_t)(k0 + kr) * NANS + n] : 0.f;
        }
        __syncthreads();
#pragma unroll
        for (int kk = 0; kk < 16; kk++) {
            float4 a = *(const float4*)&As[kk][tm];
            float4 b = *(const float4*)&Bs[kk][tn];
            acc[0][0] += a.x*b.x; acc[0][1] += a.x*b.y; acc[0][2] += a.x*b.z; acc[0][3] += a.x*b.w;
            acc[1][0] += a.y*b.x; acc[1][1] += a.y*b.y; acc[1][2] += a.y*b.z; acc[1][3] += a.y*b.w;
            acc[2][0] += a.z*b.x; acc[2][1] += a.z*b.y; acc[2][2] += a.z*b.z; acc[2][3] += a.z*b.w;
            acc[3][0] += a.w*b.x; acc[3][1] += a.w*b.y; acc[3][2] += a.w*b.z; acc[3][3] += a.w*b.w;
        }
        __syncthreads();
    }
#pragma unroll
    for (int i = 0; i < 4; i++)
#pragma unroll
        for (int j = 0; j < 4; j++) {
            int n = bn + tn + j;
            if (n < NANS)
                out[(size_t)(bm + tm + i) * NANS + n] = acc[i][j] + bp2[n];
        }
}

// ---------------- K6: in-place row softmax over 1000 -------------------------
__global__ __launch_bounds__(256) void k_softmax(float* __restrict__ out)
{
    __shared__ float red[256];
    const int tid = threadIdx.x;
    float* p = out + (size_t)blockIdx.x * NANS;
    float v[4];
    float mx = -1e30f;
#pragma unroll
    for (int i = 0; i < 4; i++) {
        int n = tid + i * 256;
        v[i] = (n < NANS) ? p[n] : -1e30f;
        mx = fmaxf(mx, v[i]);
    }
    red[tid] = mx; __syncthreads();
    for (int s = 128; s > 0; s >>= 1) {
        if (tid < s) red[tid] = fmaxf(red[tid], red[tid + s]);
        __syncthreads();
    }
    mx = red[0]; __syncthreads();
    float sum = 0.f;
#pragma unroll
    for (int i = 0; i < 4; i++) {
        int n = tid + i * 256;
        if (n < NANS) { v[i] = expf(v[i] - mx); sum += v[i]; }
    }
    red[tid] = sum; __syncthreads();
    for (int s = 128; s > 0; s >>= 1) {
        if (tid < s) red[tid] += red[tid + s];
        __syncthreads();
    }
    float inv = 1.f / red[0];
#pragma unroll
    for (int i = 0; i < 4; i++) {
        int n = tid + i * 256;
        if (n < NANS) p[n] = v[i] * inv;
    }
}

// ---------------- launch ------------------------------------------------------
extern "C" void kernel_launch(void* const* d_in, const int* in_sizes, int n_in,
                              void* d_out, int out_size)
{
    const float* data1 = (const float*)d_in[0];
    const float* data2 = (const float*)d_in[1];
    const float* W_ih1 = (const float*)d_in[2];
    const float* W_hh1 = (const float*)d_in[3];
    const float* b1    = (const float*)d_in[4];
    const float* W_ih2 = (const float*)d_in[5];
    const float* W_hh2 = (const float*)d_in[6];
    const float* b2    = (const float*)d_in[7];
    const float* Wp1   = (const float*)d_in[8];
    const float* bp1   = (const float*)d_in[9];
    const float* Wp2   = (const float*)d_in[10];
    const float* bp2   = (const float*)d_in[11];
    float* out = (float*)d_out;

    cudaFuncSetAttribute(k_stepb<false>, cudaFuncAttributeMaxDynamicSharedMemorySize, 65536);
    cudaFuncSetAttribute(k_stepb<true>,  cudaFuncAttributeMaxDynamicSharedMemorySize, 65536);

    uint32_t* W1p;  cudaGetSymbolAddress((void**)&W1p, g_W1p);
    uint32_t* W2p;  cudaGetSymbolAddress((void**)&W2p, g_W2p);

    k_init_state<<<256, 256>>>();
    k_pack_w<<<2048, 256>>>(W_hh1, nullptr, 64, W1p);
    k_pack_w<<<4096, 256>>>(W_ih2, W_hh2, 128, W2p);
    k_xproj<<<dim3(64, 128), 256>>>(data1, data2, W_ih1, b1);
    for (int t = 0; t < NT; t++) {
        k_stepb<false><<<64, 256, 65536>>>(t, nullptr);
        k_stepb<true ><<<64, 256, 65536>>>(t, b2);
    }
    k_mlp1<<<dim3(4, 128), 256>>>(Wp1, bp1);
    k_logits<<<dim3(16, 128), 256>>>(Wp2, bp2, out);
    k_softmax<<<BT, 256>>>(out);
}

// round 4
// speedup vs baseline: 8.0088x; 1.6691x over previous
#include <cuda_runtime.h>
#include <cuda_bf16.h>
#include <cstdint>
#include <math.h>

#define NB   64
#define NT   128
#define BT   8192
#define H    1024
#define DIN  2048
#define G4   4096
#define NH1  256
#define NANS 1000
#define NCTA 128u

// ---------------- device scratch ----------------
__device__ float g_X1[(size_t)BT * G4];          // [t][b][4H] (includes +b1)
__device__ float g_lstm_out[(size_t)BT * H];     // [b*NT+t][H]
__device__ float g_hid[(size_t)BT * NH1];
__device__ float g_h1f[NB * H];                  // fp32 h1_t for residual
__device__ float g_c1[NB * H];
__device__ float g_c2[NB * H];
__device__ unsigned g_bar;
// h in bf16 A-fragment layout: [kc(64)][mt(4)][lane(32)][reg(4)] u32
__device__ __align__(16) uint32_t g_h1p[2][32768];
__device__ __align__(16) uint32_t g_h2p[2][32768];
// step weights, B-fragment layout: [bx(128)][kc][g(4)][lane(32)] uint2
__device__ __align__(16) uint32_t g_W1p[128 * 64 * 4 * 32 * 2];     // 8 MB
__device__ __align__(16) uint32_t g_W2p[128 * 128 * 4 * 32 * 2];    // 16 MB
// xproj operands: A-frag [mb(128)][kc(128)][mt(4)][lane(32)][4] u32; B-frag [nb(64)][kc(128)][c(8)][lane] uint2
__device__ __align__(16) uint32_t g_Ax[(size_t)128 * 128 * 4 * 32 * 4];  // 32 MB
__device__ __align__(16) uint32_t g_Wx[(size_t)64 * 128 * 8 * 32 * 2];   // 16 MB

__device__ __forceinline__ float sigmoidf_(float x) { return 1.f / (1.f + expf(-x)); }
__device__ __forceinline__ uint32_t pk(float x, float y) {
    __nv_bfloat162 v = __floats2bfloat162_rn(x, y);
    return *reinterpret_cast<uint32_t*>(&v);
}
__device__ __forceinline__ void mmabf(float c[4], uint4 a, uint2 b) {
    asm volatile(
        "mma.sync.aligned.m16n8k16.row.col.f32.bf16.bf16.f32 "
        "{%0,%1,%2,%3},{%4,%5,%6,%7},{%8,%9},{%0,%1,%2,%3};"
        : "+f"(c[0]), "+f"(c[1]), "+f"(c[2]), "+f"(c[3])
        : "r"(a.x), "r"(a.y), "r"(a.z), "r"(a.w), "r"(b.x), "r"(b.y));
}
__device__ __forceinline__ void cp16(void* smem, const void* g) {
    uint32_t s = (uint32_t)__cvta_generic_to_shared(smem);
    asm volatile("cp.async.cg.shared.global [%0], [%1], 16;" :: "r"(s), "l"(g));
}
__device__ __forceinline__ void cp_commit() { asm volatile("cp.async.commit_group;"); }
__device__ __forceinline__ void cp_wait2()  { asm volatile("cp.async.wait_group 2;"); }
__device__ __forceinline__ void cp_wait0()  { asm volatile("cp.async.wait_group 0;"); }

// global barrier: monotonically increasing arrive counter; one per step
__device__ __forceinline__ void gbar(unsigned target) {
    __syncthreads();
    if (threadIdx.x == 0) {
        __threadfence();
        atomicAdd(&g_bar, 1u);
        while (*(volatile unsigned*)&g_bar < target) { }
        __threadfence();
    }
    __syncthreads();
}

// ---------------- init (re-runs every launch / graph replay) ----------------
__global__ void k_init_state() {
    int i = blockIdx.x * blockDim.x + threadIdx.x;
    if (i == 0) g_bar = 0u;
    if (i < NB * H) { g_c1[i] = 0.f; g_c2[i] = 0.f; g_h1f[i] = 0.f; }
    if (i < 32768)  { g_h1p[0][i] = 0u; g_h2p[0][i] = 0u; }
}

// ---------------- pack step weights -> B fragments ---------------------------
__global__ void k_pack_w(const float* __restrict__ Wa, const float* __restrict__ Wb,
                         int nkc, uint2* __restrict__ out)
{
    int total = 128 * nkc * 4 * 32;
    for (int idx = blockIdx.x * blockDim.x + threadIdx.x; idx < total;
         idx += gridDim.x * blockDim.x) {
        int lane = idx & 31;
        int t1 = idx >> 5;
        int g  = t1 & 3;
        int t2 = t1 >> 2;
        int kc = t2 % nkc;
        int bx = t2 / nkc;
        int rr = lane >> 2, cc = lane & 3;
        int row = g * H + bx * 8 + rr;
        const float* W = Wa; int k0 = kc * 16 + cc * 2;
        if (kc >= 64) { W = Wb; k0 -= 1024; }
        const float* p = W + (size_t)row * H + k0;
        uint2 v; v.x = pk(p[0], p[1]); v.y = pk(p[8], p[9]);
        out[idx] = v;
    }
}

// ---------------- pack xproj A ([d1|d2] -> A fragments) ----------------------
__global__ void k_pack_a(const float* __restrict__ d1, const float* __restrict__ d2)
{
    uint4* out = (uint4*)g_Ax;
    int total = 128 * 128 * 4 * 32;
    for (int idx = blockIdx.x * blockDim.x + threadIdx.x; idx < total;
         idx += gridDim.x * blockDim.x) {
        int lane = idx & 31;
        int t1 = idx >> 5;
        int mt = t1 & 3; t1 >>= 2;
        int kc = t1 & 127;
        int mb = t1 >> 7;
        int rr = lane >> 2, cc = lane & 3;
        int r0 = mb * 64 + mt * 16 + rr, r1 = r0 + 8;
        int k0 = kc * 16 + cc * 2;
        const float *s0, *s1;
        if (k0 < 1024) { s0 = d1 + (size_t)r0 * 1024 + k0;        s1 = d1 + (size_t)r1 * 1024 + k0; }
        else           { s0 = d2 + (size_t)r0 * 1024 + k0 - 1024; s1 = d2 + (size_t)r1 * 1024 + k0 - 1024; }
        uint4 v;
        v.x = pk(s0[0], s0[1]);
        v.y = pk(s1[0], s1[1]);
        v.z = pk(s0[8], s0[9]);
        v.w = pk(s1[8], s1[9]);
        out[idx] = v;
    }
}

// ---------------- pack xproj W_ih1 -> B fragments ----------------------------
__global__ void k_pack_wx(const float* __restrict__ W)
{
    uint2* out = (uint2*)g_Wx;
    int total = 64 * 128 * 8 * 32;
    for (int idx = blockIdx.x * blockDim.x + threadIdx.x; idx < total;
         idx += gridDim.x * blockDim.x) {
        int lane = idx & 31;
        int t1 = idx >> 5;
        int c = t1 & 7; t1 >>= 3;
        int kc = t1 & 127;
        int nb = t1 >> 7;
        int rr = lane >> 2, cc = lane & 3;
        int n = nb * 64 + c * 8 + rr;
        int k0 = kc * 16 + cc * 2;
        const float* p = W + (size_t)n * DIN + k0;
        uint2 v; v.x = pk(p[0], p[1]); v.y = pk(p[8], p[9]);
        out[idx] = v;
    }
}

// =================== xproj: bf16 mma, pre-packed fragments ==================
// grid (nb=64, mb=128), 256 thr, 4-stage cp.async pipeline (64 KB smem).
__global__ __launch_bounds__(256) void k_xprojb(const float* __restrict__ bias)
{
    extern __shared__ uint4 sm[];
    const int tid = threadIdx.x, wid = tid >> 5, lane = tid & 31;
    const int mt = wid & 3, s = wid >> 2;
    const int rr = lane >> 2, cc = lane & 3;
    const int nb = blockIdx.x, mb = blockIdx.y;
    float acc[4][4] = {};
    const uint4* A4 = (const uint4*)g_Ax + (size_t)mb * 128 * 128;
    const uint4* B4 = (const uint4*)g_Wx + (size_t)nb * 128 * 128;

    auto loadst = [&](int it) {
        if (it < 32) {
            uint4* dst = sm + (it & 3) * 1024;
            const uint4* a = A4 + (size_t)it * 512;
            const uint4* b = B4 + (size_t)it * 512;
            cp16(&dst[tid],             &a[tid]);
            cp16(&dst[tid + 256],       &a[tid + 256]);
            cp16(&dst[512 + tid],       &b[tid]);
            cp16(&dst[512 + tid + 256], &b[tid + 256]);
        }
        cp_commit();
    };
    loadst(0); loadst(1); loadst(2);
    for (int it = 0; it < 32; it++) {
        cp_wait2(); __syncthreads();
        loadst(it + 3);
        const uint4* SA = sm + (it & 3) * 1024;
        const uint2* SB = (const uint2*)(SA + 512);
#pragma unroll
        for (int kcl = 0; kcl < 4; kcl++) {
            uint4 a = SA[(kcl * 4 + mt) * 32 + lane];
#pragma unroll
            for (int jn = 0; jn < 4; jn++) {
                uint2 b = SB[(kcl * 8 + s * 4 + jn) * 32 + lane];
                mmabf(acc[jn], a, b);
            }
        }
    }
#pragma unroll
    for (int jn = 0; jn < 4; jn++) {
        int col = nb * 64 + (s * 4 + jn) * 8 + cc * 2;
        float b0 = bias[col], b1 = bias[col + 1];
#pragma unroll
        for (int hh = 0; hh < 2; hh++) {
            int m = mb * 64 + mt * 16 + rr + hh * 8;
            int tt = m & 127, bb = m >> 7;
            float* o = g_X1 + ((size_t)tt * NB + bb) * G4 + col;
            o[0] = acc[jn][hh * 2 + 0] + b0;
            o[1] = acc[jn][hh * 2 + 1] + b1;
        }
    }
}

// =================== persistent recurrence kernel ===========================
// 128 CTAs, 256 thr, smem: A stages 32KB (reused as Gs) + W1 64KB + W2 128KB.
// CTA bx owns hidden cols j in [bx*8, bx*8+8). Warp (mt, s): M rows mt*16..+15,
// K-parity s. Epilogue (s==1 warps) fuses the LSTM cell and writes h directly
// in A-fragment layout (same-lane mapping).
__global__ __launch_bounds__(256) void k_recur(const float* __restrict__ b2)
{
    extern __shared__ uint4 sm[];
    const int tid = threadIdx.x, wid = tid >> 5, lane = tid & 31;
    const int mt = wid & 3, s = wid >> 2;
    const int rr = lane >> 2, cc = lane & 3;
    const int bx = blockIdx.x;
    uint2* Wsm1 = (uint2*)(sm + 2048);
    uint2* Wsm2 = (uint2*)(sm + 6144);
    float* Gs   = (float*)sm;                 // reuse A stages post-GEMM
    const int j = bx * 8 + cc * 2;

    // one-time: weights -> smem
    {
        const uint4* w1 = (const uint4*)g_W1p + (size_t)bx * 4096;
        for (int i = tid; i < 4096; i += 256) cp16(&sm[2048 + i], &w1[i]);
        const uint4* w2 = (const uint4*)g_W2p + (size_t)bx * 8192;
        for (int i = tid; i < 8192; i += 256) cp16(&sm[6144 + i], &w2[i]);
        cp_commit(); cp_wait0(); __syncthreads();
    }

    for (int t = 0; t < NT; t++) {
        // ---------------- L1: gates = h1_prev @ W1^T (+X1[t]) ----------------
        {
            float acc[4][4] = {};
            const uint4* A4 = (const uint4*)(g_h1p[t & 1]);
            auto loadst = [&](int it) {
                if (it < 16) {
                    uint4* dst = sm + (it & 3) * 512;
                    const uint4* a = A4 + (size_t)it * 512;
                    cp16(&dst[tid],       &a[tid]);
                    cp16(&dst[tid + 256], &a[tid + 256]);
                }
                cp_commit();
            };
            loadst(0); loadst(1); loadst(2);
            for (int it = 0; it < 16; it++) {
                cp_wait2(); __syncthreads();
                loadst(it + 3);
                const uint4* SA = sm + (it & 3) * 512;
#pragma unroll
                for (int kk = 0; kk < 2; kk++) {
                    int kcl = s + kk * 2;
                    uint4 a = SA[(kcl * 4 + mt) * 32 + lane];
                    int kc = it * 4 + kcl;
#pragma unroll
                    for (int g = 0; g < 4; g++) {
                        uint2 b = Wsm1[(kc * 4 + g) * 32 + lane];
                        mmabf(acc[g], a, b);
                    }
                }
            }
            cp_wait0(); __syncthreads();
            if (s == 0) {
#pragma unroll
                for (int g = 0; g < 4; g++) {
                    Gs[(mt * 16 + rr) * 36 + g * 8 + cc * 2]         = acc[g][0];
                    Gs[(mt * 16 + rr) * 36 + g * 8 + cc * 2 + 1]     = acc[g][1];
                    Gs[(mt * 16 + rr + 8) * 36 + g * 8 + cc * 2]     = acc[g][2];
                    Gs[(mt * 16 + rr + 8) * 36 + g * 8 + cc * 2 + 1] = acc[g][3];
                }
            }
            __syncthreads();
            if (s == 1) {
                const float* Xt = g_X1 + (size_t)t * NB * G4;
#pragma unroll
                for (int hh = 0; hh < 2; hh++) {
                    int m = mt * 16 + rr + hh * 8;
                    float gi0 = acc[0][hh*2]   + Gs[m*36 +      cc*2];
                    float gi1 = acc[0][hh*2+1] + Gs[m*36 +      cc*2 + 1];
                    float gf0 = acc[1][hh*2]   + Gs[m*36 +  8 + cc*2];
                    float gf1 = acc[1][hh*2+1] + Gs[m*36 +  8 + cc*2 + 1];
                    float gg0 = acc[2][hh*2]   + Gs[m*36 + 16 + cc*2];
                    float gg1 = acc[2][hh*2+1] + Gs[m*36 + 16 + cc*2 + 1];
                    float go0 = acc[3][hh*2]   + Gs[m*36 + 24 + cc*2];
                    float go1 = acc[3][hh*2+1] + Gs[m*36 + 24 + cc*2 + 1];
                    const float* xr = Xt + (size_t)m * G4 + j;
                    float2 xi = *(const float2*)xr;
                    float2 xf = *(const float2*)(xr + H);
                    float2 xg = *(const float2*)(xr + 2 * H);
                    float2 xo = *(const float2*)(xr + 3 * H);
                    gi0 += xi.x; gi1 += xi.y; gf0 += xf.x; gf1 += xf.y;
                    gg0 += xg.x; gg1 += xg.y; go0 += xo.x; go1 += xo.y;
                    float2 cp = *(const float2*)&g_c1[m * H + j];
                    float cn0 = sigmoidf_(gf0) * cp.x + sigmoidf_(gi0) * tanhf(gg0);
                    float cn1 = sigmoidf_(gf1) * cp.y + sigmoidf_(gi1) * tanhf(gg1);
                    *(float2*)&g_c1[m * H + j] = make_float2(cn0, cn1);
                    float h0 = sigmoidf_(go0) * tanhf(cn0);
                    float h1 = sigmoidf_(go1) * tanhf(cn1);
                    *(float2*)&g_h1f[m * H + j] = make_float2(h0, h1);
                    g_h1p[(t + 1) & 1][((((bx >> 1) * 4 + mt) * 32 + lane) * 4)
                                       + hh + 2 * (bx & 1)] = pk(h0, h1);
                }
            }
        }
        gbar((unsigned)(t + 1) * NCTA);   // all h1_t visible before L2
        // ---------------- L2: gates = h1_t@Wih2^T + h2_prev@Whh2^T + b2 ------
        {
            float acc[4][4] = {};
            const uint4* A4a = (const uint4*)(g_h1p[(t + 1) & 1]);
            const uint4* A4b = (const uint4*)(g_h2p[t & 1]);
            auto loadst = [&](int it) {
                if (it < 32) {
                    uint4* dst = sm + (it & 3) * 512;
                    const uint4* a = (it < 16) ? (A4a + (size_t)it * 512)
                                               : (A4b + (size_t)(it - 16) * 512);
                    cp16(&dst[tid],       &a[tid]);
                    cp16(&dst[tid + 256], &a[tid + 256]);
                }
                cp_commit();
            };
            loadst(0); loadst(1); loadst(2);
            for (int it = 0; it < 32; it++) {
                cp_wait2(); __syncthreads();
                loadst(it + 3);
                const uint4* SA = sm + (it & 3) * 512;
#pragma unroll
                for (int kk = 0; kk < 2; kk++) {
                    int kcl = s + kk * 2;
                    uint4 a = SA[(kcl * 4 + mt) * 32 + lane];
                    int kc = it * 4 + kcl;
#pragma unroll
                    for (int g = 0; g < 4; g++) {
                        uint2 b = Wsm2[(kc * 4 + g) * 32 + lane];
                        mmabf(acc[g], a, b);
                    }
                }
            }
            cp_wait0(); __syncthreads();
            if (s == 0) {
#pragma unroll
                for (int g = 0; g < 4; g++) {
                    Gs[(mt * 16 + rr) * 36 + g * 8 + cc * 2]         = acc[g][0];
                    Gs[(mt * 16 + rr) * 36 + g * 8 + cc * 2 + 1]     = acc[g][1];
                    Gs[(mt * 16 + rr + 8) * 36 + g * 8 + cc * 2]     = acc[g][2];
                    Gs[(mt * 16 + rr + 8) * 36 + g * 8 + cc * 2 + 1] = acc[g][3];
                }
            }
            __syncthreads();
            if (s == 1) {
#pragma unroll
                for (int hh = 0; hh < 2; hh++) {
                    int m = mt * 16 + rr + hh * 8;
                    float gi0 = acc[0][hh*2]   + Gs[m*36 +      cc*2]     + b2[j];
                    float gi1 = acc[0][hh*2+1] + Gs[m*36 +      cc*2 + 1] + b2[j + 1];
                    float gf0 = acc[1][hh*2]   + Gs[m*36 +  8 + cc*2]     + b2[H + j];
                    float gf1 = acc[1][hh*2+1] + Gs[m*36 +  8 + cc*2 + 1] + b2[H + j + 1];
                    float gg0 = acc[2][hh*2]   + Gs[m*36 + 16 + cc*2]     + b2[2*H + j];
                    float gg1 = acc[2][hh*2+1] + Gs[m*36 + 16 + cc*2 + 1] + b2[2*H + j + 1];
                    float go0 = acc[3][hh*2]   + Gs[m*36 + 24 + cc*2]     + b2[3*H + j];
                    float go1 = acc[3][hh*2+1] + Gs[m*36 + 24 + cc*2 + 1] + b2[3*H + j + 1];
                    float2 cp = *(const float2*)&g_c2[m * H + j];
                    float cn0 = sigmoidf_(gf0) * cp.x + sigmoidf_(gi0) * tanhf(gg0);
                    float cn1 = sigmoidf_(gf1) * cp.y + sigmoidf_(gi1) * tanhf(gg1);
                    *(float2*)&g_c2[m * H + j] = make_float2(cn0, cn1);
                    float h0 = sigmoidf_(go0) * tanhf(cn0);
                    float h1 = sigmoidf_(go1) * tanhf(cn1);
                    g_h2p[(t + 1) & 1][((((bx >> 1) * 4 + mt) * 32 + lane) * 4)
                                       + hh + 2 * (bx & 1)] = pk(h0, h1);
                    float2 r1 = *(const float2*)&g_h1f[m * H + j];
                    *(float2*)&g_lstm_out[((size_t)m * NT + t) * H + j] =
                        make_float2(h0 + r1.x, h1 + r1.y);
                }
            }
            __syncthreads();   // Gs/A-buffer reuse safety before next L1
        }
    }
}

// ---------------- MLP head (fp32; small) --------------------------------------
__global__ __launch_bounds__(256) void k_mlp1(
    const float* __restrict__ Wp1, const float* __restrict__ bp1)
{
    __shared__ float As[16][64];
    __shared__ float Bs[16][64];
    const int bm = blockIdx.y * 64;
    const int bn = blockIdx.x * 64;
    const int tid = threadIdx.x;
    const int tm = (tid >> 4) * 4;
    const int tn = (tid & 15) * 4;
    const int lr = tid >> 2;
    const int lk = (tid & 3) * 4;
    const int kr = tid >> 4;
    const int ln = (tid & 15) * 4;
    float acc[4][4] = {};

    for (int k0 = 0; k0 < H; k0 += 16) {
        float4 av = *(const float4*)(g_lstm_out + (size_t)(bm + lr) * H + k0 + lk);
        As[lk+0][lr] = av.x; As[lk+1][lr] = av.y; As[lk+2][lr] = av.z; As[lk+3][lr] = av.w;
        float4 bv = *(const float4*)(Wp1 + (size_t)(k0 + kr) * NH1 + bn + ln);
        *(float4*)&Bs[kr][ln] = bv;
        __syncthreads();
#pragma unroll
        for (int kk = 0; kk < 16; kk++) {
            float4 a = *(const float4*)&As[kk][tm];
            float4 b = *(const float4*)&Bs[kk][tn];
            acc[0][0] += a.x*b.x; acc[0][1] += a.x*b.y; acc[0][2] += a.x*b.z; acc[0][3] += a.x*b.w;
            acc[1][0] += a.y*b.x; acc[1][1] += a.y*b.y; acc[1][2] += a.y*b.z; acc[1][3] += a.y*b.w;
            acc[2][0] += a.z*b.x; acc[2][1] += a.z*b.y; acc[2][2] += a.z*b.z; acc[2][3] += a.z*b.w;
            acc[3][0] += a.w*b.x; acc[3][1] += a.w*b.y; acc[3][2] += a.w*b.z; acc[3][3] += a.w*b.w;
        }
        __syncthreads();
    }
#pragma unroll
    for (int i = 0; i < 4; i++)
#pragma unroll
        for (int j = 0; j < 4; j++) {
            float v = acc[i][j] + bp1[bn + tn + j];
            g_hid[(size_t)(bm + tm + i) * NH1 + bn + tn + j] = fmaxf(v, 0.f);
        }
}

__global__ __launch_bounds__(256) void k_logits(
    const float* __restrict__ Wp2, const float* __restrict__ bp2,
    float* __restrict__ out)
{
    __shared__ float As[16][64];
    __shared__ float Bs[16][64];
    const int bm = blockIdx.y * 64;
    const int bn = blockIdx.x * 64;
    const int tid = threadIdx.x;
    const int tm = (tid >> 4) * 4;
    const int tn = (tid & 15) * 4;
    const int lr = tid >> 2;
    const int lk = (tid & 3) * 4;
    const int kr = tid >> 4;
    const int ln = (tid & 15) * 4;
    float acc[4][4] = {};

    for (int k0 = 0; k0 < NH1; k0 += 16) {
        float4 av = *(const float4*)(g_hid + (size_t)(bm + lr) * NH1 + k0 + lk);
        As[lk+0][lr] = av.x; As[lk+1][lr] = av.y; As[lk+2][lr] = av.z; As[lk+3][lr] = av.w;
#pragma unroll
        for (int i = 0; i < 4; i++) {
            int n = bn + ln + i;
            Bs[kr][ln + i] = (n < NANS) ? Wp2[(size_t)(k0 + kr) * NANS + n] : 0.f;
        }
        __syncthreads();
#pragma unroll
        for (int kk = 0; kk < 16; kk++) {
            float4 a = *(const float4*)&As[kk][tm];
            float4 b = *(const float4*)&Bs[kk][tn];
            acc[0][0] += a.x*b.x; acc[0][1] += a.x*b.y; acc[0][2] += a.x*b.z; acc[0][3] += a.x*b.w;
            acc[1][0] += a.y*b.x; acc[1][1] += a.y*b.y; acc[1][2] += a.y*b.z; acc[1][3] += a.y*b.w;
            acc[2][0] += a.z*b.x; acc[2][1] += a.z*b.y; acc[2][2] += a.z*b.z; acc[2][3] += a.z*b.w;
            acc[3][0] += a.w*b.x; acc[3][1] += a.w*b.y; acc[3][2] += a.w*b.z; acc[3][3] += a.w*b.w;
        }
        __syncthreads();
    }
#pragma unroll
    for (int i = 0; i < 4; i++)
#pragma unroll
        for (int j = 0; j < 4; j++) {
            int n = bn + tn + j;
            if (n < NANS)
                out[(size_t)(bm + tm + i) * NANS + n] = acc[i][j] + bp2[n];
        }
}

__global__ __launch_bounds__(256) void k_softmax(float* __restrict__ out)
{
    __shared__ float red[256];
    const int tid = threadIdx.x;
    float* p = out + (size_t)blockIdx.x * NANS;
    float v[4];
    float mx = -1e30f;
#pragma unroll
    for (int i = 0; i < 4; i++) {
        int n = tid + i * 256;
        v[i] = (n < NANS) ? p[n] : -1e30f;
        mx = fmaxf(mx, v[i]);
    }
    red[tid] = mx; __syncthreads();
    for (int s = 128; s > 0; s >>= 1) {
        if (tid < s) red[tid] = fmaxf(red[tid], red[tid + s]);
        __syncthreads();
    }
    mx = red[0]; __syncthreads();
    float sum = 0.f;
#pragma unroll
    for (int i = 0; i < 4; i++) {
        int n = tid + i * 256;
        if (n < NANS) { v[i] = expf(v[i] - mx); sum += v[i]; }
    }
    red[tid] = sum; __syncthreads();
    for (int s = 128; s > 0; s >>= 1) {
        if (tid < s) red[tid] += red[tid + s];
        __syncthreads();
    }
    float inv = 1.f / red[0];
#pragma unroll
    for (int i = 0; i < 4; i++) {
        int n = tid + i * 256;
        if (n < NANS) p[n] = v[i] * inv;
    }
}

// ---------------- launch ------------------------------------------------------
extern "C" void kernel_launch(void* const* d_in, const int* in_sizes, int n_in,
                              void* d_out, int out_size)
{
    const float* data1 = (const float*)d_in[0];
    const float* data2 = (const float*)d_in[1];
    const float* W_ih1 = (const float*)d_in[2];
    const float* W_hh1 = (const float*)d_in[3];
    const float* b1    = (const float*)d_in[4];
    const float* W_ih2 = (const float*)d_in[5];
    const float* W_hh2 = (const float*)d_in[6];
    const float* b2    = (const float*)d_in[7];
    const float* Wp1   = (const float*)d_in[8];
    const float* bp1   = (const float*)d_in[9];
    const float* Wp2   = (const float*)d_in[10];
    const float* bp2   = (const float*)d_in[11];
    float* out = (float*)d_out;

    static bool attr_done = false;
    if (!attr_done) {
        cudaFuncSetAttribute(k_xprojb, cudaFuncAttributeMaxDynamicSharedMemorySize, 65536);
        cudaFuncSetAttribute(k_recur,  cudaFuncAttributeMaxDynamicSharedMemorySize, 229376);
        attr_done = true;
    }

    uint2* W1p; cudaGetSymbolAddress((void**)&W1p, g_W1p);
    uint2* W2p; cudaGetSymbolAddress((void**)&W2p, g_W2p);

    k_init_state<<<256, 256>>>();
    k_pack_w<<<1024, 256>>>(W_hh1, nullptr, 64, W1p);
    k_pack_w<<<2048, 256>>>(W_ih2, W_hh2, 128, W2p);
    k_pack_a<<<4096, 256>>>(data1, data2);
    k_pack_wx<<<4096, 256>>>(W_ih1);
    k_xprojb<<<dim3(64, 128), 256, 65536>>>(b1);
    k_recur<<<128, 256, 229376>>>(b2);
    k_mlp1<<<dim3(4, 128), 256>>>(Wp1, bp1);
    k_logits<<<dim3(16, 128), 256>>>(Wp2, bp2, out);
    k_softmax<<<BT, 256>>>(out);
}

// round 5
// speedup vs baseline: 8.7382x; 1.0911x over previous
#include <cuda_runtime.h>
#include <cuda_bf16.h>
#include <cstdint>
#include <math.h>

#define NB   64
#define NT   128
#define BT   8192
#define H    1024
#define DIN  2048
#define G4   4096
#define NH1  256
#define NANS 1000
#define NCTA 128u

// ---------------- device scratch ----------------
__device__ float g_X1[(size_t)BT * G4];          // [t][b][4H] (includes +b1)
__device__ float g_h1f[NB * H];                  // fp32 h1_t for residual
__device__ float g_c1[NB * H];
__device__ float g_c2[NB * H];
__device__ unsigned g_bar;
// h in bf16 A-fragment layout: [kc(64)][mt(4)][lane(32)][reg(4)] u32
__device__ __align__(16) uint32_t g_h1p[2][32768];
__device__ __align__(16) uint32_t g_h2p[2][32768];
// step weights, B-fragment layout: [bx(128)][kc][g(4)][lane(32)] uint2
__device__ __align__(16) uint32_t g_W1p[128 * 64 * 4 * 32 * 2];     // 8 MB
__device__ __align__(16) uint32_t g_W2p[128 * 128 * 4 * 32 * 2];    // 16 MB
// xproj operands
__device__ __align__(16) uint32_t g_Ax[(size_t)128 * 128 * 4 * 32 * 4];  // 32 MB
__device__ __align__(16) uint32_t g_Wx[(size_t)64 * 128 * 8 * 32 * 2];   // 16 MB
// head: lstm_out bf16 A-frag [mb(128)][kc(64)][mt(4)][lane(32)][reg(4)]
__device__ __align__(16) uint32_t g_LOp[(size_t)128 * 64 * 4 * 32 * 4];  // 16 MB
// hid bf16 A-frag [mb(128)][kc(16)][mt][lane][reg]
__device__ __align__(16) uint32_t g_HIDp[(size_t)128 * 16 * 4 * 32 * 4]; // 4 MB
// Wp1 B-frag [nb(4)][kc(64)][c(8)][lane(32)] uint2 ; Wp2 padded [nb(16)][kc(16)][c(8)][lane]
__device__ __align__(16) uint32_t g_Wp1p[4 * 64 * 8 * 32 * 2];
__device__ __align__(16) uint32_t g_Wp2p[16 * 16 * 8 * 32 * 2];

__device__ __forceinline__ float sigmoidf_(float x) { return 1.f / (1.f + expf(-x)); }
__device__ __forceinline__ uint32_t pk(float x, float y) {
    __nv_bfloat162 v = __floats2bfloat162_rn(x, y);
    return *reinterpret_cast<uint32_t*>(&v);
}
__device__ __forceinline__ void mmabf(float c[4], uint4 a, uint2 b) {
    asm volatile(
        "mma.sync.aligned.m16n8k16.row.col.f32.bf16.bf16.f32 "
        "{%0,%1,%2,%3},{%4,%5,%6,%7},{%8,%9},{%0,%1,%2,%3};"
        : "+f"(c[0]), "+f"(c[1]), "+f"(c[2]), "+f"(c[3])
        : "r"(a.x), "r"(a.y), "r"(a.z), "r"(a.w), "r"(b.x), "r"(b.y));
}
__device__ __forceinline__ void cp16(void* smem, const void* g) {
    uint32_t s = (uint32_t)__cvta_generic_to_shared(smem);
    asm volatile("cp.async.cg.shared.global [%0], [%1], 16;" :: "r"(s), "l"(g));
}
__device__ __forceinline__ void cp_commit() { asm volatile("cp.async.commit_group;"); }
__device__ __forceinline__ void cp_wait2()  { asm volatile("cp.async.wait_group 2;"); }
__device__ __forceinline__ void cp_wait0()  { asm volatile("cp.async.wait_group 0;"); }

__device__ __forceinline__ void gbar(unsigned target) {
    __syncthreads();
    if (threadIdx.x == 0) {
        __threadfence();
        atomicAdd(&g_bar, 1u);
        while (*(volatile unsigned*)&g_bar < target) { }
        __threadfence();
    }
    __syncthreads();
}

// ---------------- init ----------------
__global__ void k_init_state() {
    int i = blockIdx.x * blockDim.x + threadIdx.x;
    if (i == 0) g_bar = 0u;
    if (i < NB * H) { g_c1[i] = 0.f; g_c2[i] = 0.f; g_h1f[i] = 0.f; }
    if (i < 32768)  { g_h1p[0][i] = 0u; g_h2p[0][i] = 0u; }
}

// ---------------- pack step weights -> B fragments ---------------------------
__global__ void k_pack_w(const float* __restrict__ Wa, const float* __restrict__ Wb,
                         int nkc, uint2* __restrict__ out)
{
    int total = 128 * nkc * 4 * 32;
    for (int idx = blockIdx.x * blockDim.x + threadIdx.x; idx < total;
         idx += gridDim.x * blockDim.x) {
        int lane = idx & 31;
        int t1 = idx >> 5;
        int g  = t1 & 3;
        int t2 = t1 >> 2;
        int kc = t2 % nkc;
        int bx = t2 / nkc;
        int rr = lane >> 2, cc = lane & 3;
        int row = g * H + bx * 8 + rr;
        const float* W = Wa; int k0 = kc * 16 + cc * 2;
        if (kc >= 64) { W = Wb; k0 -= 1024; }
        const float* p = W + (size_t)row * H + k0;
        uint2 v; v.x = pk(p[0], p[1]); v.y = pk(p[8], p[9]);
        out[idx] = v;
    }
}

// ---------------- pack xproj A ------------------------------------------------
__global__ void k_pack_a(const float* __restrict__ d1, const float* __restrict__ d2)
{
    uint4* out = (uint4*)g_Ax;
    int total = 128 * 128 * 4 * 32;
    for (int idx = blockIdx.x * blockDim.x + threadIdx.x; idx < total;
         idx += gridDim.x * blockDim.x) {
        int lane = idx & 31;
        int t1 = idx >> 5;
        int mt = t1 & 3; t1 >>= 2;
        int kc = t1 & 127;
        int mb = t1 >> 7;
        int rr = lane >> 2, cc = lane & 3;
        int r0 = mb * 64 + mt * 16 + rr, r1 = r0 + 8;
        int k0 = kc * 16 + cc * 2;
        const float *s0, *s1;
        if (k0 < 1024) { s0 = d1 + (size_t)r0 * 1024 + k0;        s1 = d1 + (size_t)r1 * 1024 + k0; }
        else           { s0 = d2 + (size_t)r0 * 1024 + k0 - 1024; s1 = d2 + (size_t)r1 * 1024 + k0 - 1024; }
        uint4 v;
        v.x = pk(s0[0], s0[1]);
        v.y = pk(s1[0], s1[1]);
        v.z = pk(s0[8], s0[9]);
        v.w = pk(s1[8], s1[9]);
        out[idx] = v;
    }
}

// ---------------- pack xproj W_ih1 --------------------------------------------
__global__ void k_pack_wx(const float* __restrict__ W)
{
    uint2* out = (uint2*)g_Wx;
    int total = 64 * 128 * 8 * 32;
    for (int idx = blockIdx.x * blockDim.x + threadIdx.x; idx < total;
         idx += gridDim.x * blockDim.x) {
        int lane = idx & 31;
        int t1 = idx >> 5;
        int c = t1 & 7; t1 >>= 3;
        int kc = t1 & 127;
        int nb = t1 >> 7;
        int rr = lane >> 2, cc = lane & 3;
        int n = nb * 64 + c * 8 + rr;
        int k0 = kc * 16 + cc * 2;
        const float* p = W + (size_t)n * DIN + k0;
        uint2 v; v.x = pk(p[0], p[1]); v.y = pk(p[8], p[9]);
        out[idx] = v;
    }
}

// ---------------- pack Wp1 [1024][256] (k-major) -> B-frag --------------------
__global__ void k_pack_wp1(const float* __restrict__ W)
{
    uint2* out = (uint2*)g_Wp1p;
    int total = 4 * 64 * 8 * 32;
    for (int idx = blockIdx.x * blockDim.x + threadIdx.x; idx < total;
         idx += gridDim.x * blockDim.x) {
        int lane = idx & 31;
        int t1 = idx >> 5;
        int c = t1 & 7; t1 >>= 3;
        int kc = t1 & 63;
        int nb = t1 >> 6;
        int rr = lane >> 2, cc = lane & 3;
        int n  = nb * 64 + c * 8 + rr;
        int k0 = kc * 16 + cc * 2;
        uint2 v;
        v.x = pk(W[(size_t)k0 * NH1 + n],       W[(size_t)(k0 + 1) * NH1 + n]);
        v.y = pk(W[(size_t)(k0 + 8) * NH1 + n], W[(size_t)(k0 + 9) * NH1 + n]);
        out[idx] = v;
    }
}

// ---------------- pack Wp2 [256][1000] -> B-frag (N padded to 1024) -----------
__global__ void k_pack_wp2(const float* __restrict__ W)
{
    uint2* out = (uint2*)g_Wp2p;
    int total = 16 * 16 * 8 * 32;
    for (int idx = blockIdx.x * blockDim.x + threadIdx.x; idx < total;
         idx += gridDim.x * blockDim.x) {
        int lane = idx & 31;
        int t1 = idx >> 5;
        int c = t1 & 7; t1 >>= 3;
        int kc = t1 & 15;
        int nb = t1 >> 4;
        int rr = lane >> 2, cc = lane & 3;
        int n  = nb * 64 + c * 8 + rr;
        int k0 = kc * 16 + cc * 2;
        float a0 = 0.f, a1 = 0.f, b0 = 0.f, b1 = 0.f;
        if (n < NANS) {
            a0 = W[(size_t)k0 * NANS + n];       a1 = W[(size_t)(k0 + 1) * NANS + n];
            b0 = W[(size_t)(k0 + 8) * NANS + n]; b1 = W[(size_t)(k0 + 9) * NANS + n];
        }
        uint2 v; v.x = pk(a0, a1); v.y = pk(b0, b1);
        out[idx] = v;
    }
}

// =================== xproj: bf16 mma, pre-packed fragments ==================
__global__ __launch_bounds__(256) void k_xprojb(const float* __restrict__ bias)
{
    extern __shared__ uint4 sm[];
    const int tid = threadIdx.x, wid = tid >> 5, lane = tid & 31;
    const int mt = wid & 3, s = wid >> 2;
    const int rr = lane >> 2, cc = lane & 3;
    const int nb = blockIdx.x, mb = blockIdx.y;
    float acc[4][4] = {};
    const uint4* A4 = (const uint4*)g_Ax + (size_t)mb * 128 * 128;
    const uint4* B4 = (const uint4*)g_Wx + (size_t)nb * 128 * 128;

    auto loadst = [&](int it) {
        if (it < 32) {
            uint4* dst = sm + (it & 3) * 1024;
            const uint4* a = A4 + (size_t)it * 512;
            const uint4* b = B4 + (size_t)it * 512;
            cp16(&dst[tid],             &a[tid]);
            cp16(&dst[tid + 256],       &a[tid + 256]);
            cp16(&dst[512 + tid],       &b[tid]);
            cp16(&dst[512 + tid + 256], &b[tid + 256]);
        }
        cp_commit();
    };
    loadst(0); loadst(1); loadst(2);
    for (int it = 0; it < 32; it++) {
        cp_wait2(); __syncthreads();
        loadst(it + 3);
        const uint4* SA = sm + (it & 3) * 1024;
        const uint2* SB = (const uint2*)(SA + 512);
#pragma unroll
        for (int kcl = 0; kcl < 4; kcl++) {
            uint4 a = SA[(kcl * 4 + mt) * 32 + lane];
#pragma unroll
            for (int jn = 0; jn < 4; jn++) {
                uint2 b = SB[(kcl * 8 + s * 4 + jn) * 32 + lane];
                mmabf(acc[jn], a, b);
            }
        }
    }
#pragma unroll
    for (int jn = 0; jn < 4; jn++) {
        int col = nb * 64 + (s * 4 + jn) * 8 + cc * 2;
        float b0 = bias[col], b1 = bias[col + 1];
#pragma unroll
        for (int hh = 0; hh < 2; hh++) {
            int m = mb * 64 + mt * 16 + rr + hh * 8;
            int tt = m & 127, bb = m >> 7;
            float* o = g_X1 + ((size_t)tt * NB + bb) * G4 + col;
            o[0] = acc[jn][hh * 2 + 0] + b0;
            o[1] = acc[jn][hh * 2 + 1] + b1;
        }
    }
}

// =================== persistent recurrence kernel ===========================
__global__ __launch_bounds__(256) void k_recur(const float* __restrict__ b2)
{
    extern __shared__ uint4 sm[];
    const int tid = threadIdx.x, wid = tid >> 5, lane = tid & 31;
    const int mt = wid & 3, s = wid >> 2;
    const int rr = lane >> 2, cc = lane & 3;
    const int bx = blockIdx.x;
    uint2* Wsm1 = (uint2*)(sm + 2048);
    uint2* Wsm2 = (uint2*)(sm + 6144);
    float* Gs   = (float*)sm;
    const int j = bx * 8 + cc * 2;

    {
        const uint4* w1 = (const uint4*)g_W1p + (size_t)bx * 4096;
        for (int i = tid; i < 4096; i += 256) cp16(&sm[2048 + i], &w1[i]);
        const uint4* w2 = (const uint4*)g_W2p + (size_t)bx * 8192;
        for (int i = tid; i < 8192; i += 256) cp16(&sm[6144 + i], &w2[i]);
        cp_commit(); cp_wait0(); __syncthreads();
    }

    for (int t = 0; t < NT; t++) {
        // ---------------- L1 ----------------
        {
            float acc[4][4] = {};
            const uint4* A4 = (const uint4*)(g_h1p[t & 1]);
            auto loadst = [&](int it) {
                if (it < 16) {
                    uint4* dst = sm + (it & 3) * 512;
                    const uint4* a = A4 + (size_t)it * 512;
                    cp16(&dst[tid],       &a[tid]);
                    cp16(&dst[tid + 256], &a[tid + 256]);
                }
                cp_commit();
            };
            loadst(0); loadst(1); loadst(2);
            for (int it = 0; it < 16; it++) {
                cp_wait2(); __syncthreads();
                loadst(it + 3);
                const uint4* SA = sm + (it & 3) * 512;
#pragma unroll
                for (int kk = 0; kk < 2; kk++) {
                    int kcl = s + kk * 2;
                    uint4 a = SA[(kcl * 4 + mt) * 32 + lane];
                    int kc = it * 4 + kcl;
#pragma unroll
                    for (int g = 0; g < 4; g++) {
                        uint2 b = Wsm1[(kc * 4 + g) * 32 + lane];
                        mmabf(acc[g], a, b);
                    }
                }
            }
            cp_wait0(); __syncthreads();
            if (s == 0) {
#pragma unroll
                for (int g = 0; g < 4; g++) {
                    Gs[(mt * 16 + rr) * 36 + g * 8 + cc * 2]         = acc[g][0];
                    Gs[(mt * 16 + rr) * 36 + g * 8 + cc * 2 + 1]     = acc[g][1];
                    Gs[(mt * 16 + rr + 8) * 36 + g * 8 + cc * 2]     = acc[g][2];
                    Gs[(mt * 16 + rr + 8) * 36 + g * 8 + cc * 2 + 1] = acc[g][3];
                }
            }
            __syncthreads();
            if (s == 1) {
                const float* Xt = g_X1 + (size_t)t * NB * G4;
#pragma unroll
                for (int hh = 0; hh < 2; hh++) {
                    int m = mt * 16 + rr + hh * 8;
                    float gi0 = acc[0][hh*2]   + Gs[m*36 +      cc*2];
                    float gi1 = acc[0][hh*2+1] + Gs[m*36 +      cc*2 + 1];
                    float gf0 = acc[1][hh*2]   + Gs[m*36 +  8 + cc*2];
                    float gf1 = acc[1][hh*2+1] + Gs[m*36 +  8 + cc*2 + 1];
                    float gg0 = acc[2][hh*2]   + Gs[m*36 + 16 + cc*2];
                    float gg1 = acc[2][hh*2+1] + Gs[m*36 + 16 + cc*2 + 1];
                    float go0 = acc[3][hh*2]   + Gs[m*36 + 24 + cc*2];
                    float go1 = acc[3][hh*2+1] + Gs[m*36 + 24 + cc*2 + 1];
                    const float* xr = Xt + (size_t)m * G4 + j;
                    float2 xi = *(const float2*)xr;
                    float2 xf = *(const float2*)(xr + H);
                    float2 xg = *(const float2*)(xr + 2 * H);
                    float2 xo = *(const float2*)(xr + 3 * H);
                    gi0 += xi.x; gi1 += xi.y; gf0 += xf.x; gf1 += xf.y;
                    gg0 += xg.x; gg1 += xg.y; go0 += xo.x; go1 += xo.y;
                    float2 cp = *(const float2*)&g_c1[m * H + j];
                    float cn0 = sigmoidf_(gf0) * cp.x + sigmoidf_(gi0) * tanhf(gg0);
                    float cn1 = sigmoidf_(gf1) * cp.y + sigmoidf_(gi1) * tanhf(gg1);
                    *(float2*)&g_c1[m * H + j] = make_float2(cn0, cn1);
                    float h0 = sigmoidf_(go0) * tanhf(cn0);
                    float h1 = sigmoidf_(go1) * tanhf(cn1);
                    *(float2*)&g_h1f[m * H + j] = make_float2(h0, h1);
                    g_h1p[(t + 1) & 1][((((bx >> 1) * 4 + mt) * 32 + lane) * 4)
                                       + hh + 2 * (bx & 1)] = pk(h0, h1);
                }
            }
        }
        gbar((unsigned)(t + 1) * NCTA);
        // ---------------- L2 ----------------
        {
            float acc[4][4] = {};
            const uint4* A4a = (const uint4*)(g_h1p[(t + 1) & 1]);
            const uint4* A4b = (const uint4*)(g_h2p[t & 1]);
            auto loadst = [&](int it) {
                if (it < 32) {
                    uint4* dst = sm + (it & 3) * 512;
                    const uint4* a = (it < 16) ? (A4a + (size_t)it * 512)
                                               : (A4b + (size_t)(it - 16) * 512);
                    cp16(&dst[tid],       &a[tid]);
                    cp16(&dst[tid + 256], &a[tid + 256]);
                }
                cp_commit();
            };
            loadst(0); loadst(1); loadst(2);
            for (int it = 0; it < 32; it++) {
                cp_wait2(); __syncthreads();
                loadst(it + 3);
                const uint4* SA = sm + (it & 3) * 512;
#pragma unroll
                for (int kk = 0; kk < 2; kk++) {
                    int kcl = s + kk * 2;
                    uint4 a = SA[(kcl * 4 + mt) * 32 + lane];
                    int kc = it * 4 + kcl;
#pragma unroll
                    for (int g = 0; g < 4; g++) {
                        uint2 b = Wsm2[(kc * 4 + g) * 32 + lane];
                        mmabf(acc[g], a, b);
                    }
                }
            }
            cp_wait0(); __syncthreads();
            if (s == 0) {
#pragma unroll
                for (int g = 0; g < 4; g++) {
                    Gs[(mt * 16 + rr) * 36 + g * 8 + cc * 2]         = acc[g][0];
                    Gs[(mt * 16 + rr) * 36 + g * 8 + cc * 2 + 1]     = acc[g][1];
                    Gs[(mt * 16 + rr + 8) * 36 + g * 8 + cc * 2]     = acc[g][2];
                    Gs[(mt * 16 + rr + 8) * 36 + g * 8 + cc * 2 + 1] = acc[g][3];
                }
            }
            __syncthreads();
            if (s == 1) {
#pragma unroll
                for (int hh = 0; hh < 2; hh++) {
                    int m = mt * 16 + rr + hh * 8;
                    float gi0 = acc[0][hh*2]   + Gs[m*36 +      cc*2]     + b2[j];
                    float gi1 = acc[0][hh*2+1] + Gs[m*36 +      cc*2 + 1] + b2[j + 1];
                    float gf0 = acc[1][hh*2]   + Gs[m*36 +  8 + cc*2]     + b2[H + j];
                    float gf1 = acc[1][hh*2+1] + Gs[m*36 +  8 + cc*2 + 1] + b2[H + j + 1];
                    float gg0 = acc[2][hh*2]   + Gs[m*36 + 16 + cc*2]     + b2[2*H + j];
                    float gg1 = acc[2][hh*2+1] + Gs[m*36 + 16 + cc*2 + 1] + b2[2*H + j + 1];
                    float go0 = acc[3][hh*2]   + Gs[m*36 + 24 + cc*2]     + b2[3*H + j];
                    float go1 = acc[3][hh*2+1] + Gs[m*36 + 24 + cc*2 + 1] + b2[3*H + j + 1];
                    float2 cp = *(const float2*)&g_c2[m * H + j];
                    float cn0 = sigmoidf_(gf0) * cp.x + sigmoidf_(gi0) * tanhf(gg0);
                    float cn1 = sigmoidf_(gf1) * cp.y + sigmoidf_(gi1) * tanhf(gg1);
                    *(float2*)&g_c2[m * H + j] = make_float2(cn0, cn1);
                    float h0 = sigmoidf_(go0) * tanhf(cn0);
                    float h1 = sigmoidf_(go1) * tanhf(cn1);
                    g_h2p[(t + 1) & 1][((((bx >> 1) * 4 + mt) * 32 + lane) * 4)
                                       + hh + 2 * (bx & 1)] = pk(h0, h1);
                    // residual out, written directly in head-A-fragment layout:
                    // row r = m*128 + t, colpair j
                    float2 r1 = *(const float2*)&g_h1f[m * H + j];
                    int mbL   = m * 2 + (t >> 6);
                    int kcL   = bx >> 1;
                    int mtL   = (t >> 4) & 3;
                    int laneL = (t & 7) * 4 + cc;
                    int regL  = ((t >> 3) & 1) + 2 * (bx & 1);
                    g_LOp[((((size_t)mbL * 64 + kcL) * 4 + mtL) * 32 + laneL) * 4 + regL]
                        = pk(h0 + r1.x, h1 + r1.y);
                }
            }
            __syncthreads();
        }
    }
}

// =================== head GEMM 1: hid = relu(LO @ Wp1 + bp1) =================
// M=8192, N=256, K=1024. grid (nb=4, mb=128). Writes hid in packed A-frag form.
__global__ __launch_bounds__(256) void k_mlp1b(const float* __restrict__ bp1)
{
    extern __shared__ uint4 sm[];
    const int tid = threadIdx.x, wid = tid >> 5, lane = tid & 31;
    const int mt = wid & 3, s = wid >> 2;
    const int rr = lane >> 2, cc = lane & 3;
    const int nb = blockIdx.x, mb = blockIdx.y;
    float acc[4][4] = {};
    const uint4* A4 = (const uint4*)g_LOp + (size_t)mb * 64 * 128;
    const uint4* B4 = (const uint4*)g_Wp1p + (size_t)nb * 64 * 128;

    auto loadst = [&](int it) {
        if (it < 16) {
            uint4* dst = sm + (it & 3) * 1024;
            const uint4* a = A4 + (size_t)it * 512;
            const uint4* b = B4 + (size_t)it * 512;
            cp16(&dst[tid],             &a[tid]);
            cp16(&dst[tid + 256],       &a[tid + 256]);
            cp16(&dst[512 + tid],       &b[tid]);
            cp16(&dst[512 + tid + 256], &b[tid + 256]);
        }
        cp_commit();
    };
    loadst(0); loadst(1); loadst(2);
    for (int it = 0; it < 16; it++) {
        cp_wait2(); __syncthreads();
        loadst(it + 3);
        const uint4* SA = sm + (it & 3) * 1024;
        const uint2* SB = (const uint2*)(SA + 512);
#pragma unroll
        for (int kcl = 0; kcl < 4; kcl++) {
            uint4 a = SA[(kcl * 4 + mt) * 32 + lane];
#pragma unroll
            for (int jn = 0; jn < 4; jn++) {
                uint2 b = SB[(kcl * 8 + s * 4 + jn) * 32 + lane];
                mmabf(acc[jn], a, b);
            }
        }
    }
#pragma unroll
    for (int jn = 0; jn < 4; jn++) {
        int c8  = s * 4 + jn;                    // column-of-8 index (0..7)
        int col = nb * 64 + c8 * 8 + cc * 2;
        float b0 = bp1[col], b1 = bp1[col + 1];
        int kcH = nb * 4 + (c8 >> 1);
        int regH_base = 2 * (c8 & 1);
#pragma unroll
        for (int hh = 0; hh < 2; hh++) {
            float v0 = fmaxf(acc[jn][hh * 2 + 0] + b0, 0.f);
            float v1 = fmaxf(acc[jn][hh * 2 + 1] + b1, 0.f);
            g_HIDp[((((size_t)mb * 16 + kcH) * 4 + mt) * 32 + (rr * 4 + cc)) * 4
                   + hh + regH_base] = pk(v0, v1);
        }
    }
}

// =================== head GEMM 2: logits = hid @ Wp2 + bp2 ===================
// M=8192, N=1024 (1000 valid), K=256. grid (nb=16, mb=128).
__global__ __launch_bounds__(256) void k_logitsb(const float* __restrict__ bp2,
                                                 float* __restrict__ out)
{
    extern __shared__ uint4 sm[];
    const int tid = threadIdx.x, wid = tid >> 5, lane = tid & 31;
    const int mt = wid & 3, s = wid >> 2;
    const int rr = lane >> 2, cc = lane & 3;
    const int nb = blockIdx.x, mb = blockIdx.y;
    float acc[4][4] = {};
    const uint4* A4 = (const uint4*)g_HIDp + (size_t)mb * 16 * 128;
    const uint4* B4 = (const uint4*)g_Wp2p + (size_t)nb * 16 * 128;

    auto loadst = [&](int it) {
        if (it < 4) {
            uint4* dst = sm + (it & 3) * 1024;
            const uint4* a = A4 + (size_t)it * 512;
            const uint4* b = B4 + (size_t)it * 512;
            cp16(&dst[tid],             &a[tid]);
            cp16(&dst[tid + 256],       &a[tid + 256]);
            cp16(&dst[512 + tid],       &b[tid]);
            cp16(&dst[512 + tid + 256], &b[tid + 256]);
        }
        cp_commit();
    };
    loadst(0); loadst(1); loadst(2);
    for (int it = 0; it < 4; it++) {
        cp_wait2(); __syncthreads();
        loadst(it + 3);
        const uint4* SA = sm + (it & 3) * 1024;
        const uint2* SB = (const uint2*)(SA + 512);
#pragma unroll
        for (int kcl = 0; kcl < 4; kcl++) {
            uint4 a = SA[(kcl * 4 + mt) * 32 + lane];
#pragma unroll
            for (int jn = 0; jn < 4; jn++) {
                uint2 b = SB[(kcl * 8 + s * 4 + jn) * 32 + lane];
                mmabf(acc[jn], a, b);
            }
        }
    }
#pragma unroll
    for (int jn = 0; jn < 4; jn++) {
        int n = nb * 64 + (s * 4 + jn) * 8 + cc * 2;
        if (n < NANS) {
            float b0 = bp2[n], b1 = bp2[n + 1];
#pragma unroll
            for (int hh = 0; hh < 2; hh++) {
                int m = mb * 64 + mt * 16 + rr + hh * 8;
                float* o = out + (size_t)m * NANS + n;
                o[0] = acc[jn][hh * 2 + 0] + b0;
                o[1] = acc[jn][hh * 2 + 1] + b1;
            }
        }
    }
}

// ---------------- softmax ------------------------------------------------------
__global__ __launch_bounds__(256) void k_softmax(float* __restrict__ out)
{
    __shared__ float red[256];
    const int tid = threadIdx.x;
    float* p = out + (size_t)blockIdx.x * NANS;
    float v[4];
    float mx = -1e30f;
#pragma unroll
    for (int i = 0; i < 4; i++) {
        int n = tid + i * 256;
        v[i] = (n < NANS) ? p[n] : -1e30f;
        mx = fmaxf(mx, v[i]);
    }
    red[tid] = mx; __syncthreads();
    for (int s = 128; s > 0; s >>= 1) {
        if (tid < s) red[tid] = fmaxf(red[tid], red[tid + s]);
        __syncthreads();
    }
    mx = red[0]; __syncthreads();
    float sum = 0.f;
#pragma unroll
    for (int i = 0; i < 4; i++) {
        int n = tid + i * 256;
        if (n < NANS) { v[i] = expf(v[i] - mx); sum += v[i]; }
    }
    red[tid] = sum; __syncthreads();
    for (int s = 128; s > 0; s >>= 1) {
        if (tid < s) red[tid] += red[tid + s];
        __syncthreads();
    }
    float inv = 1.f / red[0];
#pragma unroll
    for (int i = 0; i < 4; i++) {
        int n = tid + i * 256;
        if (n < NANS) p[n] = v[i] * inv;
    }
}

// ---------------- launch ------------------------------------------------------
extern "C" void kernel_launch(void* const* d_in, const int* in_sizes, int n_in,
                              void* d_out, int out_size)
{
    const float* data1 = (const float*)d_in[0];
    const float* data2 = (const float*)d_in[1];
    const float* W_ih1 = (const float*)d_in[2];
    const float* W_hh1 = (const float*)d_in[3];
    const float* b1    = (const float*)d_in[4];
    const float* W_ih2 = (const float*)d_in[5];
    const float* W_hh2 = (const float*)d_in[6];
    const float* b2    = (const float*)d_in[7];
    const float* Wp1   = (const float*)d_in[8];
    const float* bp1   = (const float*)d_in[9];
    const float* Wp2   = (const float*)d_in[10];
    const float* bp2   = (const float*)d_in[11];
    float* out = (float*)d_out;

    static bool attr_done = false;
    if (!attr_done) {
        cudaFuncSetAttribute(k_xprojb,  cudaFuncAttributeMaxDynamicSharedMemorySize, 65536);
        cudaFuncSetAttribute(k_mlp1b,   cudaFuncAttributeMaxDynamicSharedMemorySize, 65536);
        cudaFuncSetAttribute(k_logitsb, cudaFuncAttributeMaxDynamicSharedMemorySize, 65536);
        cudaFuncSetAttribute(k_recur,   cudaFuncAttributeMaxDynamicSharedMemorySize, 229376);
        attr_done = true;
    }

    uint2* W1p; cudaGetSymbolAddress((void**)&W1p, g_W1p);
    uint2* W2p; cudaGetSymbolAddress((void**)&W2p, g_W2p);

    k_init_state<<<256, 256>>>();
    k_pack_w<<<1024, 256>>>(W_hh1, nullptr, 64, W1p);
    k_pack_w<<<2048, 256>>>(W_ih2, W_hh2, 128, W2p);
    k_pack_a<<<4096, 256>>>(data1, data2);
    k_pack_wx<<<4096, 256>>>(W_ih1);
    k_pack_wp1<<<256, 256>>>(Wp1);
    k_pack_wp2<<<256, 256>>>(Wp2);
    k_xprojb<<<dim3(64, 128), 256, 65536>>>(b1);
    k_recur<<<128, 256, 229376>>>(b2);
    k_mlp1b<<<dim3(4, 128), 256, 65536>>>(bp1);
    k_logitsb<<<dim3(16, 128), 256, 65536>>>(bp2, out);
    k_softmax<<<BT, 256>>>(out);
}

// round 6
// speedup vs baseline: 9.2026x; 1.0531x over previous
#include <cuda_runtime.h>
#include <cuda_bf16.h>
#include <cstdint>
#include <math.h>

#define NB   64
#define NT   128
#define BT   8192
#define H    1024
#define DIN  2048
#define G4   4096
#define NH1  256
#define NANS 1000
#define NCTA 128u

// ---------------- device scratch ----------------
__device__ float g_X1[(size_t)BT * G4];          // [t][b][4H] (includes +b1)
__device__ float g_c1[NB * H];
__device__ float g_c2[NB * H];
__device__ unsigned g_bar;
// h in bf16 A-fragment layout: [kc(64)][mt(4)][lane(32)][reg(4)] u32
__device__ __align__(16) uint32_t g_h1p[2][32768];
__device__ __align__(16) uint32_t g_h2p[2][32768];
// step weights, B-fragment layout: [bx(128)][kc][g(4)][lane(32)] uint2
__device__ __align__(16) uint32_t g_W1p[128 * 64 * 4 * 32 * 2];     // 8 MB
__device__ __align__(16) uint32_t g_W2p[128 * 128 * 4 * 32 * 2];    // 16 MB
// xproj operands
__device__ __align__(16) uint32_t g_Ax[(size_t)128 * 128 * 4 * 32 * 4];  // 32 MB
__device__ __align__(16) uint32_t g_Wx[(size_t)64 * 128 * 8 * 32 * 2];   // 16 MB
// head: lstm_out bf16 A-frag [mb(128)][kc(64)][mt(4)][lane(32)][reg(4)]
__device__ __align__(16) uint32_t g_LOp[(size_t)128 * 64 * 4 * 32 * 4];  // 16 MB
// hid bf16 A-frag [mb(128)][kc(16)][mt][lane][reg]
__device__ __align__(16) uint32_t g_HIDp[(size_t)128 * 16 * 4 * 32 * 4]; // 4 MB
__device__ __align__(16) uint32_t g_Wp1p[4 * 64 * 8 * 32 * 2];
__device__ __align__(16) uint32_t g_Wp2p[16 * 16 * 8 * 32 * 2];

__device__ __forceinline__ float sigmoidf_(float x) { return 1.f / (1.f + expf(-x)); }
__device__ __forceinline__ uint32_t pk(float x, float y) {
    __nv_bfloat162 v = __floats2bfloat162_rn(x, y);
    return *reinterpret_cast<uint32_t*>(&v);
}
__device__ __forceinline__ void mmabf(float c[4], uint4 a, uint2 b) {
    asm volatile(
        "mma.sync.aligned.m16n8k16.row.col.f32.bf16.bf16.f32 "
        "{%0,%1,%2,%3},{%4,%5,%6,%7},{%8,%9},{%0,%1,%2,%3};"
        : "+f"(c[0]), "+f"(c[1]), "+f"(c[2]), "+f"(c[3])
        : "r"(a.x), "r"(a.y), "r"(a.z), "r"(a.w), "r"(b.x), "r"(b.y));
}
__device__ __forceinline__ void cp16(void* smem, const void* g) {
    uint32_t s = (uint32_t)__cvta_generic_to_shared(smem);
    asm volatile("cp.async.cg.shared.global [%0], [%1], 16;" :: "r"(s), "l"(g));
}
__device__ __forceinline__ void cp_commit() { asm volatile("cp.async.commit_group;"); }
__device__ __forceinline__ void cp_wait2()  { asm volatile("cp.async.wait_group 2;"); }
__device__ __forceinline__ void cp_wait0()  { asm volatile("cp.async.wait_group 0;"); }

__device__ __forceinline__ void gbar(unsigned target) {
    __syncthreads();
    if (threadIdx.x == 0) {
        __threadfence();
        atomicAdd(&g_bar, 1u);
        while (*(volatile unsigned*)&g_bar < target) { }
        __threadfence();
    }
    __syncthreads();
}

// ---------------- init ----------------
__global__ void k_init_state() {
    int i = blockIdx.x * blockDim.x + threadIdx.x;
    if (i == 0) g_bar = 0u;
    if (i < NB * H) { g_c1[i] = 0.f; g_c2[i] = 0.f; }
    if (i < 32768)  { g_h1p[0][i] = 0u; g_h2p[0][i] = 0u; }
}

// ---------------- pack step weights -> B fragments ---------------------------
__global__ void k_pack_w(const float* __restrict__ Wa, const float* __restrict__ Wb,
                         int nkc, uint2* __restrict__ out)
{
    int total = 128 * nkc * 4 * 32;
    for (int idx = blockIdx.x * blockDim.x + threadIdx.x; idx < total;
         idx += gridDim.x * blockDim.x) {
        int lane = idx & 31;
        int t1 = idx >> 5;
        int g  = t1 & 3;
        int t2 = t1 >> 2;
        int kc = t2 % nkc;
        int bx = t2 / nkc;
        int rr = lane >> 2, cc = lane & 3;
        int row = g * H + bx * 8 + rr;
        const float* W = Wa; int k0 = kc * 16 + cc * 2;
        if (kc >= 64) { W = Wb; k0 -= 1024; }
        const float* p = W + (size_t)row * H + k0;
        uint2 v; v.x = pk(p[0], p[1]); v.y = pk(p[8], p[9]);
        out[idx] = v;
    }
}

// ---------------- pack xproj A ------------------------------------------------
__global__ void k_pack_a(const float* __restrict__ d1, const float* __restrict__ d2)
{
    uint4* out = (uint4*)g_Ax;
    int total = 128 * 128 * 4 * 32;
    for (int idx = blockIdx.x * blockDim.x + threadIdx.x; idx < total;
         idx += gridDim.x * blockDim.x) {
        int lane = idx & 31;
        int t1 = idx >> 5;
        int mt = t1 & 3; t1 >>= 2;
        int kc = t1 & 127;
        int mb = t1 >> 7;
        int rr = lane >> 2, cc = lane & 3;
        int r0 = mb * 64 + mt * 16 + rr, r1 = r0 + 8;
        int k0 = kc * 16 + cc * 2;
        const float *s0, *s1;
        if (k0 < 1024) { s0 = d1 + (size_t)r0 * 1024 + k0;        s1 = d1 + (size_t)r1 * 1024 + k0; }
        else           { s0 = d2 + (size_t)r0 * 1024 + k0 - 1024; s1 = d2 + (size_t)r1 * 1024 + k0 - 1024; }
        uint4 v;
        v.x = pk(s0[0], s0[1]);
        v.y = pk(s1[0], s1[1]);
        v.z = pk(s0[8], s0[9]);
        v.w = pk(s1[8], s1[9]);
        out[idx] = v;
    }
}

// ---------------- pack xproj W_ih1 --------------------------------------------
__global__ void k_pack_wx(const float* __restrict__ W)
{
    uint2* out = (uint2*)g_Wx;
    int total = 64 * 128 * 8 * 32;
    for (int idx = blockIdx.x * blockDim.x + threadIdx.x; idx < total;
         idx += gridDim.x * blockDim.x) {
        int lane = idx & 31;
        int t1 = idx >> 5;
        int c = t1 & 7; t1 >>= 3;
        int kc = t1 & 127;
        int nb = t1 >> 7;
        int rr = lane >> 2, cc = lane & 3;
        int n = nb * 64 + c * 8 + rr;
        int k0 = kc * 16 + cc * 2;
        const float* p = W + (size_t)n * DIN + k0;
        uint2 v; v.x = pk(p[0], p[1]); v.y = pk(p[8], p[9]);
        out[idx] = v;
    }
}

// ---------------- pack Wp1 / Wp2 ------------------------------------------------
__global__ void k_pack_wp1(const float* __restrict__ W)
{
    uint2* out = (uint2*)g_Wp1p;
    int total = 4 * 64 * 8 * 32;
    for (int idx = blockIdx.x * blockDim.x + threadIdx.x; idx < total;
         idx += gridDim.x * blockDim.x) {
        int lane = idx & 31;
        int t1 = idx >> 5;
        int c = t1 & 7; t1 >>= 3;
        int kc = t1 & 63;
        int nb = t1 >> 6;
        int rr = lane >> 2, cc = lane & 3;
        int n  = nb * 64 + c * 8 + rr;
        int k0 = kc * 16 + cc * 2;
        uint2 v;
        v.x = pk(W[(size_t)k0 * NH1 + n],       W[(size_t)(k0 + 1) * NH1 + n]);
        v.y = pk(W[(size_t)(k0 + 8) * NH1 + n], W[(size_t)(k0 + 9) * NH1 + n]);
        out[idx] = v;
    }
}

__global__ void k_pack_wp2(const float* __restrict__ W)
{
    uint2* out = (uint2*)g_Wp2p;
    int total = 16 * 16 * 8 * 32;
    for (int idx = blockIdx.x * blockDim.x + threadIdx.x; idx < total;
         idx += gridDim.x * blockDim.x) {
        int lane = idx & 31;
        int t1 = idx >> 5;
        int c = t1 & 7; t1 >>= 3;
        int kc = t1 & 15;
        int nb = t1 >> 4;
        int rr = lane >> 2, cc = lane & 3;
        int n  = nb * 64 + c * 8 + rr;
        int k0 = kc * 16 + cc * 2;
        float a0 = 0.f, a1 = 0.f, b0 = 0.f, b1 = 0.f;
        if (n < NANS) {
            a0 = W[(size_t)k0 * NANS + n];       a1 = W[(size_t)(k0 + 1) * NANS + n];
            b0 = W[(size_t)(k0 + 8) * NANS + n]; b1 = W[(size_t)(k0 + 9) * NANS + n];
        }
        uint2 v; v.x = pk(a0, a1); v.y = pk(b0, b1);
        out[idx] = v;
    }
}

// =================== xproj: bf16 mma, pre-packed fragments ==================
__global__ __launch_bounds__(256) void k_xprojb(const float* __restrict__ bias)
{
    extern __shared__ uint4 sm[];
    const int tid = threadIdx.x, wid = tid >> 5, lane = tid & 31;
    const int mt = wid & 3, s = wid >> 2;
    const int rr = lane >> 2, cc = lane & 3;
    const int nb = blockIdx.x, mb = blockIdx.y;
    float acc[4][4] = {};
    const uint4* A4 = (const uint4*)g_Ax + (size_t)mb * 128 * 128;
    const uint4* B4 = (const uint4*)g_Wx + (size_t)nb * 128 * 128;

    auto loadst = [&](int it) {
        if (it < 32) {
            uint4* dst = sm + (it & 3) * 1024;
            const uint4* a = A4 + (size_t)it * 512;
            const uint4* b = B4 + (size_t)it * 512;
            cp16(&dst[tid],             &a[tid]);
            cp16(&dst[tid + 256],       &a[tid + 256]);
            cp16(&dst[512 + tid],       &b[tid]);
            cp16(&dst[512 + tid + 256], &b[tid + 256]);
        }
        cp_commit();
    };
    loadst(0); loadst(1); loadst(2);
    for (int it = 0; it < 32; it++) {
        cp_wait2(); __syncthreads();
        loadst(it + 3);
        const uint4* SA = sm + (it & 3) * 1024;
        const uint2* SB = (const uint2*)(SA + 512);
#pragma unroll
        for (int kcl = 0; kcl < 4; kcl++) {
            uint4 a = SA[(kcl * 4 + mt) * 32 + lane];
#pragma unroll
            for (int jn = 0; jn < 4; jn++) {
                uint2 b = SB[(kcl * 8 + s * 4 + jn) * 32 + lane];
                mmabf(acc[jn], a, b);
            }
        }
    }
#pragma unroll
    for (int jn = 0; jn < 4; jn++) {
        int col = nb * 64 + (s * 4 + jn) * 8 + cc * 2;
        float b0 = bias[col], b1 = bias[col + 1];
#pragma unroll
        for (int hh = 0; hh < 2; hh++) {
            int m = mb * 64 + mt * 16 + rr + hh * 8;
            int tt = m & 127, bb = m >> 7;
            float* o = g_X1 + ((size_t)tt * NB + bb) * G4 + col;
            o[0] = acc[jn][hh * 2 + 0] + b0;
            o[1] = acc[jn][hh * 2 + 1] + b1;
        }
    }
}

// =================== persistent recurrence kernel ===========================
// A fragments have NO intra-CTA reuse -> load them straight from L2 (__ldcg),
// register ring depth 2. Weights stay smem-resident. ~5 syncs/step total.
// smem (uint4 units): Gs [0,576) ; W1 [576, 4672) ; W2 [4672, 12864)
__global__ __launch_bounds__(256) void k_recur(const float* __restrict__ b2)
{
    extern __shared__ uint4 sm[];
    const int tid = threadIdx.x, wid = tid >> 5, lane = tid & 31;
    const int mt = wid & 3, s = wid >> 2;
    const int rr = lane >> 2, cc = lane & 3;
    const int bx = blockIdx.x;
    float* Gs   = (float*)sm;
    const uint2* Wsm1 = (const uint2*)(sm + 576);
    const uint2* Wsm2 = (const uint2*)(sm + 4672);
    const int j = bx * 8 + cc * 2;

    // weights -> smem (one time)
    {
        const uint4* w1 = (const uint4*)g_W1p + (size_t)bx * 4096;
        for (int i = tid; i < 4096; i += 256) cp16(&sm[576 + i], &w1[i]);
        const uint4* w2 = (const uint4*)g_W2p + (size_t)bx * 8192;
        for (int i = tid; i < 8192; i += 256) cp16(&sm[4672 + i], &w2[i]);
        cp_commit(); cp_wait0(); __syncthreads();
    }

    // per-thread epilogue constants (s==1 threads only use them)
    float2 b2i = make_float2(b2[j],         b2[j + 1]);
    float2 b2f = make_float2(b2[H + j],     b2[H + j + 1]);
    float2 b2g = make_float2(b2[2 * H + j], b2[2 * H + j + 1]);
    float2 b2o = make_float2(b2[3 * H + j], b2[3 * H + j + 1]);

    float2 h1res[2];   // register carry of h1_t for the residual (s==1)

    for (int t = 0; t < NT; t++) {
        // ================= L1: gates = h1_prev @ W1^T + X1[t] ================
        {
            const uint4* A4 = (const uint4*)(g_h1p[t & 1]);
            float acc[4][4] = {};
            uint4 abuf[2][2];
            auto lda = [&](int q, uint4* d) {
                d[0] = __ldcg(A4 + ((q * 4 + s    ) * 4 + mt) * 32 + lane);
                d[1] = __ldcg(A4 + ((q * 4 + s + 2) * 4 + mt) * 32 + lane);
            };
            lda(0, abuf[0]); lda(1, abuf[1]);
#pragma unroll
            for (int q = 0; q < 16; q++) {
                uint4 c0 = abuf[q & 1][0], c1 = abuf[q & 1][1];
                if (q + 2 < 16) lda(q + 2, abuf[q & 1]);
                const int kc0 = q * 4 + s, kc1 = kc0 + 2;
#pragma unroll
                for (int g = 0; g < 4; g++)
                    mmabf(acc[g], c0, Wsm1[(kc0 * 4 + g) * 32 + lane]);
#pragma unroll
                for (int g = 0; g < 4; g++)
                    mmabf(acc[g], c1, Wsm1[(kc1 * 4 + g) * 32 + lane]);
            }
            __syncthreads();                       // Gs free (prev step done)
            if (s == 0) {
#pragma unroll
                for (int g = 0; g < 4; g++) {
                    Gs[(mt * 16 + rr) * 36 + g * 8 + cc * 2]         = acc[g][0];
                    Gs[(mt * 16 + rr) * 36 + g * 8 + cc * 2 + 1]     = acc[g][1];
                    Gs[(mt * 16 + rr + 8) * 36 + g * 8 + cc * 2]     = acc[g][2];
                    Gs[(mt * 16 + rr + 8) * 36 + g * 8 + cc * 2 + 1] = acc[g][3];
                }
            }
            __syncthreads();
            if (s == 1) {
                const float* Xt = g_X1 + (size_t)t * NB * G4;
#pragma unroll
                for (int hh = 0; hh < 2; hh++) {
                    int m = mt * 16 + rr + hh * 8;
                    float gi0 = acc[0][hh*2]   + Gs[m*36 +      cc*2];
                    float gi1 = acc[0][hh*2+1] + Gs[m*36 +      cc*2 + 1];
                    float gf0 = acc[1][hh*2]   + Gs[m*36 +  8 + cc*2];
                    float gf1 = acc[1][hh*2+1] + Gs[m*36 +  8 + cc*2 + 1];
                    float gg0 = acc[2][hh*2]   + Gs[m*36 + 16 + cc*2];
                    float gg1 = acc[2][hh*2+1] + Gs[m*36 + 16 + cc*2 + 1];
                    float go0 = acc[3][hh*2]   + Gs[m*36 + 24 + cc*2];
                    float go1 = acc[3][hh*2+1] + Gs[m*36 + 24 + cc*2 + 1];
                    const float* xr = Xt + (size_t)m * G4 + j;
                    float2 xi = *(const float2*)xr;
                    float2 xf = *(const float2*)(xr + H);
                    float2 xg = *(const float2*)(xr + 2 * H);
                    float2 xo = *(const float2*)(xr + 3 * H);
                    gi0 += xi.x; gi1 += xi.y; gf0 += xf.x; gf1 += xf.y;
                    gg0 += xg.x; gg1 += xg.y; go0 += xo.x; go1 += xo.y;
                    float2 cp = *(const float2*)&g_c1[m * H + j];
                    float cn0 = sigmoidf_(gf0) * cp.x + sigmoidf_(gi0) * tanhf(gg0);
                    float cn1 = sigmoidf_(gf1) * cp.y + sigmoidf_(gi1) * tanhf(gg1);
                    *(float2*)&g_c1[m * H + j] = make_float2(cn0, cn1);
                    float h0 = sigmoidf_(go0) * tanhf(cn0);
                    float h1 = sigmoidf_(go1) * tanhf(cn1);
                    h1res[hh] = make_float2(h0, h1);
                    g_h1p[(t + 1) & 1][((((bx >> 1) * 4 + mt) * 32 + lane) * 4)
                                       + hh + 2 * (bx & 1)] = pk(h0, h1);
                }
            }
        }
        gbar((unsigned)(t + 1) * NCTA);            // all h1_t visible
        // ======= L2: gates = h1_t@Wih2^T + h2_prev@Whh2^T + b2, residual =====
        {
            const uint4* A4a = (const uint4*)(g_h1p[(t + 1) & 1]);
            const uint4* A4b = (const uint4*)(g_h2p[t & 1]);
            float acc[4][4] = {};
            uint4 abuf[2][2];
            auto lda2 = [&](int q, uint4* d) {
                const int k0 = q * 4 + s, k1 = k0 + 2;
                const uint4* p0 = (k0 < 64) ? (A4a + (k0 * 4 + mt) * 32 + lane)
                                            : (A4b + ((k0 - 64) * 4 + mt) * 32 + lane);
                const uint4* p1 = (k1 < 64) ? (A4a + (k1 * 4 + mt) * 32 + lane)
                                            : (A4b + ((k1 - 64) * 4 + mt) * 32 + lane);
                d[0] = __ldcg(p0); d[1] = __ldcg(p1);
            };
            lda2(0, abuf[0]); lda2(1, abuf[1]);
#pragma unroll
            for (int q = 0; q < 32; q++) {
                uint4 c0 = abuf[q & 1][0], c1 = abuf[q & 1][1];
                if (q + 2 < 32) lda2(q + 2, abuf[q & 1]);
                const int kc0 = q * 4 + s, kc1 = kc0 + 2;
#pragma unroll
                for (int g = 0; g < 4; g++)
                    mmabf(acc[g], c0, Wsm2[(kc0 * 4 + g) * 32 + lane]);
#pragma unroll
                for (int g = 0; g < 4; g++)
                    mmabf(acc[g], c1, Wsm2[(kc1 * 4 + g) * 32 + lane]);
            }
            __syncthreads();
            if (s == 0) {
#pragma unroll
                for (int g = 0; g < 4; g++) {
                    Gs[(mt * 16 + rr) * 36 + g * 8 + cc * 2]         = acc[g][0];
                    Gs[(mt * 16 + rr) * 36 + g * 8 + cc * 2 + 1]     = acc[g][1];
                    Gs[(mt * 16 + rr + 8) * 36 + g * 8 + cc * 2]     = acc[g][2];
                    Gs[(mt * 16 + rr + 8) * 36 + g * 8 + cc * 2 + 1] = acc[g][3];
                }
            }
            __syncthreads();
            if (s == 1) {
#pragma unroll
                for (int hh = 0; hh < 2; hh++) {
                    int m = mt * 16 + rr + hh * 8;
                    float gi0 = acc[0][hh*2]   + Gs[m*36 +      cc*2]     + b2i.x;
                    float gi1 = acc[0][hh*2+1] + Gs[m*36 +      cc*2 + 1] + b2i.y;
                    float gf0 = acc[1][hh*2]   + Gs[m*36 +  8 + cc*2]     + b2f.x;
                    float gf1 = acc[1][hh*2+1] + Gs[m*36 +  8 + cc*2 + 1] + b2f.y;
                    float gg0 = acc[2][hh*2]   + Gs[m*36 + 16 + cc*2]     + b2g.x;
                    float gg1 = acc[2][hh*2+1] + Gs[m*36 + 16 + cc*2 + 1] + b2g.y;
                    float go0 = acc[3][hh*2]   + Gs[m*36 + 24 + cc*2]     + b2o.x;
                    float go1 = acc[3][hh*2+1] + Gs[m*36 + 24 + cc*2 + 1] + b2o.y;
                    float2 cp = *(const float2*)&g_c2[m * H + j];
                    float cn0 = sigmoidf_(gf0) * cp.x + sigmoidf_(gi0) * tanhf(gg0);
                    float cn1 = sigmoidf_(gf1) * cp.y + sigmoidf_(gi1) * tanhf(gg1);
                    *(float2*)&g_c2[m * H + j] = make_float2(cn0, cn1);
                    float h0 = sigmoidf_(go0) * tanhf(cn0);
                    float h1 = sigmoidf_(go1) * tanhf(cn1);
                    g_h2p[(t + 1) & 1][((((bx >> 1) * 4 + mt) * 32 + lane) * 4)
                                       + hh + 2 * (bx & 1)] = pk(h0, h1);
                    // residual out in head-A-fragment layout (row = m*128+t)
                    int mbL   = m * 2 + (t >> 6);
                    int kcL   = bx >> 1;
                    int mtL   = (t >> 4) & 3;
                    int laneL = (t & 7) * 4 + cc;
                    int regL  = ((t >> 3) & 1) + 2 * (bx & 1);
                    g_LOp[((((size_t)mbL * 64 + kcL) * 4 + mtL) * 32 + laneL) * 4 + regL]
                        = pk(h0 + h1res[hh].x, h1 + h1res[hh].y);
                }
            }
        }
    }
}

// =================== head GEMM 1: hid = relu(LO @ Wp1 + bp1) =================
__global__ __launch_bounds__(256) void k_mlp1b(const float* __restrict__ bp1)
{
    extern __shared__ uint4 sm[];
    const int tid = threadIdx.x, wid = tid >> 5, lane = tid & 31;
    const int mt = wid & 3, s = wid >> 2;
    const int rr = lane >> 2, cc = lane & 3;
    const int nb = blockIdx.x, mb = blockIdx.y;
    float acc[4][4] = {};
    const uint4* A4 = (const uint4*)g_LOp + (size_t)mb * 64 * 128;
    const uint4* B4 = (const uint4*)g_Wp1p + (size_t)nb * 64 * 128;

    auto loadst = [&](int it) {
        if (it < 16) {
            uint4* dst = sm + (it & 3) * 1024;
            const uint4* a = A4 + (size_t)it * 512;
            const uint4* b = B4 + (size_t)it * 512;
            cp16(&dst[tid],             &a[tid]);
            cp16(&dst[tid + 256],       &a[tid + 256]);
            cp16(&dst[512 + tid],       &b[tid]);
            cp16(&dst[512 + tid + 256], &b[tid + 256]);
        }
        cp_commit();
    };
    loadst(0); loadst(1); loadst(2);
    for (int it = 0; it < 16; it++) {
        cp_wait2(); __syncthreads();
        loadst(it + 3);
        const uint4* SA = sm + (it & 3) * 1024;
        const uint2* SB = (const uint2*)(SA + 512);
#pragma unroll
        for (int kcl = 0; kcl < 4; kcl++) {
            uint4 a = SA[(kcl * 4 + mt) * 32 + lane];
#pragma unroll
            for (int jn = 0; jn < 4; jn++) {
                uint2 b = SB[(kcl * 8 + s * 4 + jn) * 32 + lane];
                mmabf(acc[jn], a, b);
            }
        }
    }
#pragma unroll
    for (int jn = 0; jn < 4; jn++) {
        int c8  = s * 4 + jn;
        int col = nb * 64 + c8 * 8 + cc * 2;
        float b0 = bp1[col], b1 = bp1[col + 1];
        int kcH = nb * 4 + (c8 >> 1);
        int regH_base = 2 * (c8 & 1);
#pragma unroll
        for (int hh = 0; hh < 2; hh++) {
            float v0 = fmaxf(acc[jn][hh * 2 + 0] + b0, 0.f);
            float v1 = fmaxf(acc[jn][hh * 2 + 1] + b1, 0.f);
            g_HIDp[((((size_t)mb * 16 + kcH) * 4 + mt) * 32 + (rr * 4 + cc)) * 4
                   + hh + regH_base] = pk(v0, v1);
        }
    }
}

// =================== head GEMM 2: logits = hid @ Wp2 + bp2 ===================
__global__ __launch_bounds__(256) void k_logitsb(const float* __restrict__ bp2,
                                                 float* __restrict__ out)
{
    extern __shared__ uint4 sm[];
    const int tid = threadIdx.x, wid = tid >> 5, lane = tid & 31;
    const int mt = wid & 3, s = wid >> 2;
    const int rr = lane >> 2, cc = lane & 3;
    const int nb = blockIdx.x, mb = blockIdx.y;
    float acc[4][4] = {};
    const uint4* A4 = (const uint4*)g_HIDp + (size_t)mb * 16 * 128;
    const uint4* B4 = (const uint4*)g_Wp2p + (size_t)nb * 16 * 128;

    auto loadst = [&](int it) {
        if (it < 4) {
            uint4* dst = sm + (it & 3) * 1024;
            const uint4* a = A4 + (size_t)it * 512;
            const uint4* b = B4 + (size_t)it * 512;
            cp16(&dst[tid],             &a[tid]);
            cp16(&dst[tid + 256],       &a[tid + 256]);
            cp16(&dst[512 + tid],       &b[tid]);
            cp16(&dst[512 + tid + 256], &b[tid + 256]);
        }
        cp_commit();
    };
    loadst(0); loadst(1); loadst(2);
    for (int it = 0; it < 4; it++) {
        cp_wait2(); __syncthreads();
        loadst(it + 3);
        const uint4* SA = sm + (it & 3) * 1024;
        const uint2* SB = (const uint2*)(SA + 512);
#pragma unroll
        for (int kcl = 0; kcl < 4; kcl++) {
            uint4 a = SA[(kcl * 4 + mt) * 32 + lane];
#pragma unroll
            for (int jn = 0; jn < 4; jn++) {
                uint2 b = SB[(kcl * 8 + s * 4 + jn) * 32 + lane];
                mmabf(acc[jn], a, b);
            }
        }
    }
#pragma unroll
    for (int jn = 0; jn < 4; jn++) {
        int n = nb * 64 + (s * 4 + jn) * 8 + cc * 2;
        if (n < NANS) {
            float b0 = bp2[n], b1 = bp2[n + 1];
#pragma unroll
            for (int hh = 0; hh < 2; hh++) {
                int m = mb * 64 + mt * 16 + rr + hh * 8;
                float* o = out + (size_t)m * NANS + n;
                o[0] = acc[jn][hh * 2 + 0] + b0;
                o[1] = acc[jn][hh * 2 + 1] + b1;
            }
        }
    }
}

// ---------------- softmax ------------------------------------------------------
__global__ __launch_bounds__(256) void k_softmax(float* __restrict__ out)
{
    __shared__ float red[256];
    const int tid = threadIdx.x;
    float* p = out + (size_t)blockIdx.x * NANS;
    float v[4];
    float mx = -1e30f;
#pragma unroll
    for (int i = 0; i < 4; i++) {
        int n = tid + i * 256;
        v[i] = (n < NANS) ? p[n] : -1e30f;
        mx = fmaxf(mx, v[i]);
    }
    red[tid] = mx; __syncthreads();
    for (int s = 128; s > 0; s >>= 1) {
        if (tid < s) red[tid] = fmaxf(red[tid], red[tid + s]);
        __syncthreads();
    }
    mx = red[0]; __syncthreads();
    float sum = 0.f;
#pragma unroll
    for (int i = 0; i < 4; i++) {
        int n = tid + i * 256;
        if (n < NANS) { v[i] = expf(v[i] - mx); sum += v[i]; }
    }
    red[tid] = sum; __syncthreads();
    for (int s = 128; s > 0; s >>= 1) {
        if (tid < s) red[tid] += red[tid + s];
        __syncthreads();
    }
    float inv = 1.f / red[0];
#pragma unroll
    for (int i = 0; i < 4; i++) {
        int n = tid + i * 256;
        if (n < NANS) p[n] = v[i] * inv;
    }
}

// ---------------- launch ------------------------------------------------------
extern "C" void kernel_launch(void* const* d_in, const int* in_sizes, int n_in,
                              void* d_out, int out_size)
{
    const float* data1 = (const float*)d_in[0];
    const float* data2 = (const float*)d_in[1];
    const float* W_ih1 = (const float*)d_in[2];
    const float* W_hh1 = (const float*)d_in[3];
    const float* b1    = (const float*)d_in[4];
    const float* W_ih2 = (const float*)d_in[5];
    const float* W_hh2 = (const float*)d_in[6];
    const float* b2    = (const float*)d_in[7];
    const float* Wp1   = (const float*)d_in[8];
    const float* bp1   = (const float*)d_in[9];
    const float* Wp2   = (const float*)d_in[10];
    const float* bp2   = (const float*)d_in[11];
    float* out = (float*)d_out;

    static bool attr_done = false;
    if (!attr_done) {
        cudaFuncSetAttribute(k_xprojb,  cudaFuncAttributeMaxDynamicSharedMemorySize, 65536);
        cudaFuncSetAttribute(k_mlp1b,   cudaFuncAttributeMaxDynamicSharedMemorySize, 65536);
        cudaFuncSetAttribute(k_logitsb, cudaFuncAttributeMaxDynamicSharedMemorySize, 65536);
        cudaFuncSetAttribute(k_recur,   cudaFuncAttributeMaxDynamicSharedMemorySize, 229376);
        attr_done = true;
    }

    uint2* W1p; cudaGetSymbolAddress((void**)&W1p, g_W1p);
    uint2* W2p; cudaGetSymbolAddress((void**)&W2p, g_W2p);

    k_init_state<<<256, 256>>>();
    k_pack_w<<<1024, 256>>>(W_hh1, nullptr, 64, W1p);
    k_pack_w<<<2048, 256>>>(W_ih2, W_hh2, 128, W2p);
    k_pack_a<<<4096, 256>>>(data1, data2);
    k_pack_wx<<<4096, 256>>>(W_ih1);
    k_pack_wp1<<<256, 256>>>(Wp1);
    k_pack_wp2<<<256, 256>>>(Wp2);
    k_xprojb<<<dim3(64, 128), 256, 65536>>>(b1);
    k_recur<<<128, 256, 205824>>>(b2);
    k_mlp1b<<<dim3(4, 128), 256, 65536>>>(bp1);
    k_logitsb<<<dim3(16, 128), 256, 65536>>>(bp2, out);
    k_softmax<<<BT, 256>>>(out);
}